// round 4
// baseline (speedup 1.0000x reference)
#include <cuda_runtime.h>
#include <math.h>
#include <stdint.h>

#define BS 32
#define NS 65536
#define NF 128
#define CHUNK 64
#define NCH (NS / CHUNK)      // 1024
#define SRf 48000.0f
#define STAB 0.999f

// Output plane offsets (in elements of BS*NS):
// dry=0, wet=1, env=2, y_ab=3, a_coeff3=4..6, b_coeff=7..9, y_a=10  (total 11 planes)

struct BParam {
    float inc, phase, kk, shp;
    float sm, gain, dur, alpha;
    float dist, pad0, pad1, pad2;
};

__device__ BParam g_bp[BS];
__device__ float4 g_frame[BS * NF * 2];   // per frame: {a1,a2,b0,b1},{b2,-,-,-}
__device__ float  g_chunk[BS * NCH * 6];  // m00,m01,m10,m11,p0,p1
__device__ float2 g_init[BS * NCH];

// ---- XLA rational tanh (Eigen fast tanh, used by XLA CPU & GPU EmitTanh) ----
__device__ __forceinline__ float xla_tanh(float x) {
    const float kClamp = 7.90531110763549805f;
    float xc = fminf(fmaxf(x, -kClamp), kClamp);
    float x2 = __fmul_rn(xc, xc);
    float p = __fadd_rn(2.00018790482477e-13f, __fmul_rn(x2, -2.76076847742355e-16f));
    p = __fadd_rn(-8.60467152213735e-11f, __fmul_rn(x2, p));
    p = __fadd_rn(5.12229709037114e-08f,  __fmul_rn(x2, p));
    p = __fadd_rn(1.48572235717979e-05f,  __fmul_rn(x2, p));
    p = __fadd_rn(6.37261928875436e-04f,  __fmul_rn(x2, p));
    p = __fadd_rn(4.89352455891786e-03f,  __fmul_rn(x2, p));
    float num = __fmul_rn(xc, p);
    float q = __fadd_rn(1.18534705686654e-04f, __fmul_rn(x2, 1.19825839466702e-06f));
    q = __fadd_rn(2.26843463243900e-03f, __fmul_rn(x2, q));
    q = __fadd_rn(4.89352518554385e-03f, __fmul_rn(x2, q));
    float r = __fdiv_rn(num, q);
    return (fabsf(x) < 0.0004f) ? x : r;
}

// ---- XLA-CPU-style sin/cos: range reduce with single-f32 2*pi, then accurate ----
__device__ __forceinline__ float xla_sin(float x) {
    float k = rintf(__fmul_rn(x, 0.15915494309189535f));     // fl(1/2pi)
    float r = fmaf(-k, 6.28318548202514648f, x);              // fl(2pi)
    return sinf(r);
}
__device__ __forceinline__ float xla_cos(float x) {
    float k = rintf(__fmul_rn(x, 0.15915494309189535f));
    float r = fmaf(-k, 6.28318548202514648f, x);
    return cosf(r);
}

// Bit-exact emulation of jax.lax.associative_scan cumsum of a CONSTANT c at
// index t (inclusive): all pairwise combines are exact doublings; result =
// MSB->LSB rounded adds of c*2^bit over set bits of (t+1).
__device__ __forceinline__ float xla_cumsum_const(float c, unsigned t) {
    unsigned u = t + 1u;
    int msb = 31 - __clz(u);
    float v = c * __int_as_float((127 + msb) << 23);   // exact scale by 2^msb
#pragma unroll 1
    for (int k = msb - 1; k >= 0; k--) {
        if ((u >> k) & 1u)
            v = __fadd_rn(v, c * __int_as_float((127 + k) << 23));
    }
    return v;
}

// ---------------- K0: per-batch params + per-frame biquad coeffs ----------------
__global__ void k_prep(const float* __restrict__ f0_hz,
                       const float* __restrict__ durp,
                       const float* __restrict__ phasep,
                       const float* __restrict__ logits,
                       const float* __restrict__ shpp,
                       const float* __restrict__ gainp,
                       const float* __restrict__ distp,
                       const float* __restrict__ alphap) {
    int tid = blockIdx.x * blockDim.x + threadIdx.x;
    if (tid >= BS * NF) return;
    int b = tid / NF;
    int f = tid - b * NF;
    const float* lg = logits + (size_t)tid * 5;
    float th0 = xla_tanh(lg[0]);
    float a1 = __fmul_rn(__fmul_rn(2.0f, th0), STAB);
    float a1a = fabsf(a1);
    float th1 = xla_tanh(lg[1]);
    float a2 = __fdiv_rn(__fadd_rn(__fmul_rn(__fmul_rn(__fsub_rn(2.0f, a1a), th1), STAB), a1a), 2.0f);
    g_frame[tid * 2]     = make_float4(a1, a2, lg[2], lg[3]);
    g_frame[tid * 2 + 1] = make_float4(lg[4], 0.f, 0.f, 0.f);
    if (f == 0) {
        BParam p;
        float f0 = f0_hz[b];
        p.inc = __fdiv_rn(f0, SRf);
        p.phase = phasep[b];
        float partials = __fdiv_rn(12000.0f, __fmul_rn(f0, log10f(f0)));
        p.kk = __fmul_rn(3.14159274101257324f, partials);   // fl(pi_f32 * partials)
        p.shp = shpp[b];
        p.sm = __fsub_rn(1.0f, __fmul_rn(shpp[b], 0.5f));   // 1 - s/2 (s/2 exact)
        p.gain = gainp[b];
        p.dur = durp[b];
        p.alpha = alphap[b];
        p.dist = distp[b];
        g_bp[b] = p;
    }
}

// ---------------- K1: osc + env + coeff interpolation; writes dry/env/a3/b3 ----------------
__global__ void k_main(float* __restrict__ out) {
    int tid = blockIdx.x * blockDim.x + threadIdx.x;
    if (tid >= BS * (NS / 8)) return;
    int b = tid >> 13;                 // NS/8 = 8192 threads per batch
    int s0 = (tid & 8191) << 3;
    BParam p = g_bp[b];

    float dryv[8], envv[8], a1v[8], a2v[8], b0v[8], b1v[8], b2v[8];

#pragma unroll
    for (int j = 0; j < 8; j++) {
        int i = s0 + j;
        // --- phase: bit-exact associative_scan cumsum emulation ---
        float cum = xla_cumsum_const(p.inc, (unsigned)i);
        float arg = __fadd_rn(__fmul_rn(6.28318548202514648f, cum), p.phase);
        float s = xla_sin(arg);
        float c = xla_cos(__fmul_rn(arg, 0.5f));
        float sq = xla_tanh(__fdiv_rn(__fmul_rn(p.kk, s), 2.0f));
        float vco = __fmul_rn(__fmul_rn(p.sm, sq),
                              __fadd_rn(1.0f, __fmul_rn(p.shp, c)));

        // --- envelope ---
        float tt = __fdiv_rn((float)i, SRf);
        float ramp = __fsub_rn(1.0f, __fdiv_rn(tt, p.dur));
        ramp = fminf(fmaxf(ramp, 0.001f), 1.0f);
        float env = powf(ramp, p.alpha);
        if (!(tt <= p.dur)) env = 0.0f;
        envv[j] = env;
        dryv[j] = __fmul_rn(__fmul_rn(vco, p.gain), env);

        // --- frame interpolation (align_corners linspace 0..127 over 65536) ---
        float pos = __fmul_rn((float)i, 127.0f / 65535.0f);
        float i0f = floorf(pos);
        int i0 = (int)i0f;
        i0 = min(i0, 126);
        float frc = __fsub_rn(pos, (float)i0);
        float w0 = __fsub_rn(1.0f, frc);
        float4 fA = g_frame[(b * NF + i0) * 2];
        float4 fB = g_frame[(b * NF + i0) * 2 + 1];
        float4 gA = g_frame[(b * NF + i0 + 1) * 2];
        float4 gB = g_frame[(b * NF + i0 + 1) * 2 + 1];
        a1v[j] = __fadd_rn(__fmul_rn(fA.x, w0), __fmul_rn(gA.x, frc));
        a2v[j] = __fadd_rn(__fmul_rn(fA.y, w0), __fmul_rn(gA.y, frc));
        b0v[j] = __fadd_rn(__fmul_rn(fA.z, w0), __fmul_rn(gA.z, frc));
        b1v[j] = __fadd_rn(__fmul_rn(fA.w, w0), __fmul_rn(gA.w, frc));
        b2v[j] = __fadd_rn(__fmul_rn(fB.x, w0), __fmul_rn(gB.x, frc));
    }

    size_t base = (size_t)b * NS + s0;
    float4* dptr = (float4*)(out + base);
    dptr[0] = make_float4(dryv[0], dryv[1], dryv[2], dryv[3]);
    dptr[1] = make_float4(dryv[4], dryv[5], dryv[6], dryv[7]);
    float4* eptr = (float4*)(out + 2ull * BS * NS + base);
    eptr[0] = make_float4(envv[0], envv[1], envv[2], envv[3]);
    eptr[1] = make_float4(envv[4], envv[5], envv[6], envv[7]);
    float4* aptr = (float4*)(out + 4ull * BS * NS + base * 3);
    aptr[0] = make_float4(1.0f, a1v[0], a2v[0], 1.0f);
    aptr[1] = make_float4(a1v[1], a2v[1], 1.0f, a1v[2]);
    aptr[2] = make_float4(a2v[2], 1.0f, a1v[3], a2v[3]);
    aptr[3] = make_float4(1.0f, a1v[4], a2v[4], 1.0f);
    aptr[4] = make_float4(a1v[5], a2v[5], 1.0f, a1v[6]);
    aptr[5] = make_float4(a2v[6], 1.0f, a1v[7], a2v[7]);
    float4* bptr = (float4*)(out + 7ull * BS * NS + base * 3);
    bptr[0] = make_float4(b0v[0], b1v[0], b2v[0], b0v[1]);
    bptr[1] = make_float4(b1v[1], b2v[1], b0v[2], b1v[2]);
    bptr[2] = make_float4(b2v[2], b0v[3], b1v[3], b2v[3]);
    bptr[3] = make_float4(b0v[4], b1v[4], b2v[4], b0v[5]);
    bptr[4] = make_float4(b1v[5], b2v[5], b0v[6], b1v[6]);
    bptr[5] = make_float4(b2v[6], b0v[7], b1v[7], b2v[7]);
}

// ---------------- K2: per-chunk affine transfer (pass 1) ----------------
__global__ void k_pass1(const float* __restrict__ out) {
    int tid = blockIdx.x * blockDim.x + threadIdx.x;
    if (tid >= BS * NCH) return;
    int b = tid >> 10;
    int c = tid & (NCH - 1);
    size_t base = (size_t)b * NS + (size_t)c * CHUNK;
    const float* dry = out + base;
    const float* a3 = out + 4ull * BS * NS + base * 3;

    float yp1 = 0.f, yp2 = 0.f, u1 = 1.f, u2 = 0.f, v1 = 0.f, v2 = 1.f;

    for (int g = 0; g < CHUNK; g += 8) {
        float4 x0 = *(const float4*)(dry + g);
        float4 x1 = *(const float4*)(dry + g + 4);
        float4 A[6];
#pragma unroll
        for (int q = 0; q < 6; q++) A[q] = *(const float4*)(a3 + 3 * g + 4 * q);
        const float* af = (const float*)A;
        float xs[8] = {x0.x, x0.y, x0.z, x0.w, x1.x, x1.y, x1.z, x1.w};
#pragma unroll
        for (int j = 0; j < 8; j++) {
            float a1 = af[3 * j + 1], a2 = af[3 * j + 2];
            float yp = fmaf(-a1, yp1, fmaf(-a2, yp2, xs[j]));
            float u = fmaf(-a1, u1, -(a2 * u2));
            float v = fmaf(-a1, v1, -(a2 * v2));
            yp2 = yp1; yp1 = yp;
            u2 = u1; u1 = u;
            v2 = v1; v1 = v;
        }
    }
    float* o = g_chunk + (size_t)tid * 6;
    o[0] = u1; o[1] = v1; o[2] = u2; o[3] = v2; o[4] = yp1; o[5] = yp2;
}

// ---------------- K3: per-voice affine scan over chunks ----------------
__global__ void k_scan() {
    int b = blockIdx.x;
    int lane = threadIdx.x;            // 32 lanes
    const int G = NCH / 32;            // 32 chunks per lane
    int cbase = lane * G;

    float m00 = 1.f, m01 = 0.f, m10 = 0.f, m11 = 1.f, p0 = 0.f, p1 = 0.f;
    const float* q = g_chunk + ((size_t)b * NCH + cbase) * 6;
    for (int c = 0; c < G; c++) {
        float c00 = q[0], c01 = q[1], c10 = q[2], c11 = q[3], r0 = q[4], r1 = q[5];
        float n00 = c00 * m00 + c01 * m10;
        float n01 = c00 * m01 + c01 * m11;
        float n10 = c10 * m00 + c11 * m10;
        float n11 = c10 * m01 + c11 * m11;
        float np0 = c00 * p0 + c01 * p1 + r0;
        float np1 = c10 * p0 + c11 * p1 + r1;
        m00 = n00; m01 = n01; m10 = n10; m11 = n11; p0 = np0; p1 = np1;
        q += 6;
    }
    for (int d = 1; d < 32; d <<= 1) {
        float e00 = __shfl_up_sync(0xffffffffu, m00, d);
        float e01 = __shfl_up_sync(0xffffffffu, m01, d);
        float e10 = __shfl_up_sync(0xffffffffu, m10, d);
        float e11 = __shfl_up_sync(0xffffffffu, m11, d);
        float ep0 = __shfl_up_sync(0xffffffffu, p0, d);
        float ep1 = __shfl_up_sync(0xffffffffu, p1, d);
        if (lane >= d) {
            float n00 = m00 * e00 + m01 * e10;
            float n01 = m00 * e01 + m01 * e11;
            float n10 = m10 * e00 + m11 * e10;
            float n11 = m10 * e01 + m11 * e11;
            float np0 = m00 * ep0 + m01 * ep1 + p0;
            float np1 = m10 * ep0 + m11 * ep1 + p1;
            m00 = n00; m01 = n01; m10 = n10; m11 = n11; p0 = np0; p1 = np1;
        }
    }
    float s0 = __shfl_up_sync(0xffffffffu, p0, 1);
    float s1 = __shfl_up_sync(0xffffffffu, p1, 1);
    if (lane == 0) { s0 = 0.f; s1 = 0.f; }

    q = g_chunk + ((size_t)b * NCH + cbase) * 6;
    for (int c = 0; c < G; c++) {
        g_init[(size_t)b * NCH + cbase + c] = make_float2(s0, s1);
        float c00 = q[0], c01 = q[1], c10 = q[2], c11 = q[3], r0 = q[4], r1 = q[5];
        float ns0 = c00 * s0 + c01 * s1 + r0;
        float ns1 = c10 * s0 + c11 * s1 + r1;
        s0 = ns0; s1 = ns1;
        q += 6;
    }
}

// ---------------- K4: pass 2 — IIR replay (exact ref rounding) + FIR + tanh ----------------
__global__ void k_pass2(float* __restrict__ out) {
    int tid = blockIdx.x * blockDim.x + threadIdx.x;
    if (tid >= BS * NCH) return;
    int b = tid >> 10;
    int c = tid & (NCH - 1);
    size_t base = (size_t)b * NS + (size_t)c * CHUNK;
    const float* dry = out + base;
    const float* a3 = out + 4ull * BS * NS + base * 3;
    const float* b3 = out + 7ull * BS * NS + base * 3;
    float* w_wet = out + 1ull * BS * NS + base;
    float* w_yab = out + 3ull * BS * NS + base;
    float* w_ya = out + 10ull * BS * NS + base;

    float2 ini = g_init[tid];
    float y1 = ini.x, y2 = ini.y;
    float dg = g_bp[b].dist;

    for (int g = 0; g < CHUNK; g += 8) {
        float4 x0 = *(const float4*)(dry + g);
        float4 x1 = *(const float4*)(dry + g + 4);
        float4 A[6], B[6];
#pragma unroll
        for (int q = 0; q < 6; q++) A[q] = *(const float4*)(a3 + 3 * g + 4 * q);
#pragma unroll
        for (int q = 0; q < 6; q++) B[q] = *(const float4*)(b3 + 3 * g + 4 * q);
        const float* af = (const float*)A;
        const float* bf = (const float*)B;
        float xs[8] = {x0.x, x0.y, x0.z, x0.w, x1.x, x1.y, x1.z, x1.w};
        float ya[8], yb[8], wt[8];
#pragma unroll
        for (int j = 0; j < 8; j++) {
            float a1 = af[3 * j + 1], a2 = af[3 * j + 2];
            float c0 = bf[3 * j], c1 = bf[3 * j + 1], c2 = bf[3 * j + 2];
            // exact reference rounding: y = (x - a1*y1) - a2*y2
            float y = __fsub_rn(__fsub_rn(xs[j], __fmul_rn(a1, y1)), __fmul_rn(a2, y2));
            // exact reference rounding: v = (b0*y + b1*y1) + b2*y2
            float v = __fadd_rn(__fadd_rn(__fmul_rn(c0, y), __fmul_rn(c1, y1)),
                                __fmul_rn(c2, y2));
            ya[j] = y; yb[j] = v;
            wt[j] = xla_tanh(__fmul_rn(v, dg));
            y2 = y1; y1 = y;
        }
        ((float4*)(w_ya + g))[0] = make_float4(ya[0], ya[1], ya[2], ya[3]);
        ((float4*)(w_ya + g))[1] = make_float4(ya[4], ya[5], ya[6], ya[7]);
        ((float4*)(w_yab + g))[0] = make_float4(yb[0], yb[1], yb[2], yb[3]);
        ((float4*)(w_yab + g))[1] = make_float4(yb[4], yb[5], yb[6], yb[7]);
        ((float4*)(w_wet + g))[0] = make_float4(wt[0], wt[1], wt[2], wt[3]);
        ((float4*)(w_wet + g))[1] = make_float4(wt[4], wt[5], wt[6], wt[7]);
    }
}

extern "C" void kernel_launch(void* const* d_in, const int* in_sizes, int n_in,
                              void* d_out, int out_size) {
    const float* f0_hz = (const float*)d_in[0];
    const float* note_on = (const float*)d_in[1];
    const float* phase = (const float*)d_in[2];
    const float* logits = (const float*)d_in[3];
    const float* osc_shape = (const float*)d_in[4];
    const float* osc_gain = (const float*)d_in[5];
    const float* dist_gain = (const float*)d_in[6];
    const float* learned_alpha = (const float*)d_in[7];
    float* out = (float*)d_out;

    k_prep<<<(BS * NF + 255) / 256, 256>>>(f0_hz, note_on, phase, logits,
                                           osc_shape, osc_gain, dist_gain, learned_alpha);
    k_main<<<(BS * (NS / 8) + 255) / 256, 256>>>(out);
    k_pass1<<<(BS * NCH + 255) / 256, 256>>>(out);
    k_scan<<<BS, 32>>>();
    k_pass2<<<(BS * NCH + 255) / 256, 256>>>(out);
}

// round 5
// speedup vs baseline: 1.0200x; 1.0200x over previous
#include <cuda_runtime.h>
#include <math.h>
#include <stdint.h>

#define BS 32
#define NS 65536
#define NF 128
#define CHUNK 64
#define NCH (NS / CHUNK)      // 1024
#define SRf 48000.0f
#define STAB 0.999f

// Output plane offsets (elements of BS*NS):
// dry=0, wet=1, env=2, y_ab=3, a_coeff3=4..6, b_coeff=7..9, y_a=10

struct BParam {
    float inc, phase, kk, shp;
    float sm, gain, dur, alpha;
    float dist, pad0, pad1, pad2;
};

__device__ BParam g_bp[BS];
__device__ float4 g_frame[BS * NF * 2];   // per frame: {a1,a2,b0,b1},{b2,-,-,-}
__device__ float  g_chunk[BS * NCH * 6];  // u1,v1,u2,v2,yp1,yp2
__device__ float2 g_init[BS * NCH];

// ---- XLA rational tanh (Eigen fast tanh) ----
__device__ __forceinline__ float xla_tanh(float x) {
    const float kClamp = 7.90531110763549805f;
    float xc = fminf(fmaxf(x, -kClamp), kClamp);
    float x2 = __fmul_rn(xc, xc);
    float p = __fadd_rn(2.00018790482477e-13f, __fmul_rn(x2, -2.76076847742355e-16f));
    p = __fadd_rn(-8.60467152213735e-11f, __fmul_rn(x2, p));
    p = __fadd_rn(5.12229709037114e-08f,  __fmul_rn(x2, p));
    p = __fadd_rn(1.48572235717979e-05f,  __fmul_rn(x2, p));
    p = __fadd_rn(6.37261928875436e-04f,  __fmul_rn(x2, p));
    p = __fadd_rn(4.89352455891786e-03f,  __fmul_rn(x2, p));
    float num = __fmul_rn(xc, p);
    float q = __fadd_rn(1.18534705686654e-04f, __fmul_rn(x2, 1.19825839466702e-06f));
    q = __fadd_rn(2.26843463243900e-03f, __fmul_rn(x2, q));
    q = __fadd_rn(4.89352518554385e-03f, __fmul_rn(x2, q));
    float r = __fdiv_rn(num, q);
    return (fabsf(x) < 0.0004f) ? x : r;
}

// ---- XLA-CPU-style sin/cos: range reduce with single-f32 2*pi, then accurate ----
__device__ __forceinline__ float xla_sin(float x) {
    float k = rintf(__fmul_rn(x, 0.15915494309189535f));
    float r = fmaf(-k, 6.28318548202514648f, x);
    return sinf(r);
}
__device__ __forceinline__ float xla_cos(float x) {
    float k = rintf(__fmul_rn(x, 0.15915494309189535f));
    float r = fmaf(-k, 6.28318548202514648f, x);
    return cosf(r);
}

// Chain over bits >=5 of v (v multiple of 32, v>0): MSB->LSB rounded adds.
// Prefix of the full associative-scan cumsum chain -> bit-exact base.
__device__ __forceinline__ float cum_base5(float c, unsigned v) {
    int msb = 31 - __clz(v);
    float r = c * __int_as_float((127 + msb) << 23);
#pragma unroll 1
    for (int k = msb - 1; k >= 5; k--) {
        if ((v >> k) & 1u)
            r = __fadd_rn(r, c * __int_as_float((127 + k) << 23));
    }
    return r;
}

// ---------------- K0: per-batch params + per-frame biquad coeffs ----------------
__global__ void k_prep(const float* __restrict__ f0_hz,
                       const float* __restrict__ durp,
                       const float* __restrict__ phasep,
                       const float* __restrict__ logits,
                       const float* __restrict__ shpp,
                       const float* __restrict__ gainp,
                       const float* __restrict__ distp,
                       const float* __restrict__ alphap) {
    int tid = blockIdx.x * blockDim.x + threadIdx.x;
    if (tid >= BS * NF) return;
    int b = tid / NF;
    int f = tid - b * NF;
    const float* lg = logits + (size_t)tid * 5;
    float th0 = xla_tanh(lg[0]);
    float a1 = __fmul_rn(__fmul_rn(2.0f, th0), STAB);
    float a1a = fabsf(a1);
    float th1 = xla_tanh(lg[1]);
    float a2 = __fdiv_rn(__fadd_rn(__fmul_rn(__fmul_rn(__fsub_rn(2.0f, a1a), th1), STAB), a1a), 2.0f);
    g_frame[tid * 2]     = make_float4(a1, a2, lg[2], lg[3]);
    g_frame[tid * 2 + 1] = make_float4(lg[4], 0.f, 0.f, 0.f);
    if (f == 0) {
        BParam p;
        float f0 = f0_hz[b];
        p.inc = __fdiv_rn(f0, SRf);
        p.phase = phasep[b];
        float partials = __fdiv_rn(12000.0f, __fmul_rn(f0, log10f(f0)));
        p.kk = __fmul_rn(3.14159274101257324f, partials);
        p.shp = shpp[b];
        p.sm = __fsub_rn(1.0f, __fmul_rn(shpp[b], 0.5f));
        p.gain = gainp[b];
        p.dur = durp[b];
        p.alpha = alphap[b];
        p.dist = distp[b];
        g_bp[b] = p;
    }
}

// ---------------- K1: osc + env + coeff interp + FUSED pass1 affine ----------------
// one thread = one 64-sample chunk
__global__ void k_mainp1(float* __restrict__ out) {
    int tid = blockIdx.x * blockDim.x + threadIdx.x;
    if (tid >= BS * NCH) return;
    int b = tid >> 10;
    int c = tid & (NCH - 1);
    int s0 = c << 6;
    BParam p = g_bp[b];

    // cumsum bases (bit-exact prefix chains)
    float inc = p.inc;
    float i16 = inc * 16.0f, i8 = inc * 8.0f, i4 = inc * 4.0f, i2 = inc * 2.0f;
    float baseA = (s0 == 0) ? 0.0f : cum_base5(inc, (unsigned)s0);
    float baseB = cum_base5(inc, (unsigned)(s0 + 32));
    float baseC = cum_base5(inc, (unsigned)(s0 + 64));

    // hoist frame loads: i0 spans at most one boundary within 64 samples
    float pos0 = __fmul_rn((float)s0, 127.0f / 65535.0f);
    int i0s = (int)floorf(pos0);
    i0s = min(i0s, 126);
    int i2x = min(i0s + 2, 127);
    float4 F0a = g_frame[(b * NF + i0s) * 2],     F0b = g_frame[(b * NF + i0s) * 2 + 1];
    float4 F1a = g_frame[(b * NF + i0s + 1) * 2], F1b = g_frame[(b * NF + i0s + 1) * 2 + 1];
    float4 F2a = g_frame[(b * NF + i2x) * 2],     F2b = g_frame[(b * NF + i2x) * 2 + 1];

    // affine recurrence state (pass1)
    float yp1 = 0.f, yp2 = 0.f, u1 = 1.f, u2 = 0.f, v1 = 0.f, v2 = 1.f;

    size_t vbase = (size_t)b * NS + s0;

#pragma unroll 1
    for (int g = 0; g < 8; g++) {
        float dryv[8], envv[8], a1v[8], a2v[8], b0v[8], b1v[8], b2v[8];
#pragma unroll
        for (int j = 0; j < 8; j++) {
            int jj = g * 8 + j;
            int i = s0 + jj;
            unsigned l = (unsigned)(jj + 1);
            // --- phase: bit-exact associative_scan cumsum (hoisted bases) ---
            float cum = (l < 32u) ? baseA : ((l < 64u) ? baseB : baseC);
            if (l & 16u) cum = __fadd_rn(cum, i16);
            if (l & 8u)  cum = __fadd_rn(cum, i8);
            if (l & 4u)  cum = __fadd_rn(cum, i4);
            if (l & 2u)  cum = __fadd_rn(cum, i2);
            if (l & 1u)  cum = __fadd_rn(cum, inc);
            float arg = __fadd_rn(__fmul_rn(6.28318548202514648f, cum), p.phase);
            float s = xla_sin(arg);
            float cc = xla_cos(__fmul_rn(arg, 0.5f));
            float sq = xla_tanh(__fdiv_rn(__fmul_rn(p.kk, s), 2.0f));
            float vco = __fmul_rn(__fmul_rn(p.sm, sq),
                                  __fadd_rn(1.0f, __fmul_rn(p.shp, cc)));

            // --- envelope ---
            float tt = __fdiv_rn((float)i, SRf);
            float ramp = __fsub_rn(1.0f, __fdiv_rn(tt, p.dur));
            ramp = fminf(fmaxf(ramp, 0.001f), 1.0f);
            float env = powf(ramp, p.alpha);
            if (!(tt <= p.dur)) env = 0.0f;
            envv[j] = env;
            float dj = __fmul_rn(__fmul_rn(vco, p.gain), env);
            dryv[j] = dj;

            // --- frame interpolation (identical values via hoisted frames) ---
            float pos = __fmul_rn((float)i, 127.0f / 65535.0f);
            float i0f = floorf(pos);
            int i0 = (int)i0f;
            i0 = min(i0, 126);
            float frc = __fsub_rn(pos, (float)i0);
            float w0 = __fsub_rn(1.0f, frc);
            bool hi = (i0 != i0s);
            float4 fA = hi ? F1a : F0a;
            float4 fB = hi ? F1b : F0b;
            float4 gA = hi ? F2a : F1a;
            float4 gB = hi ? F2b : F1b;
            float a1 = __fadd_rn(__fmul_rn(fA.x, w0), __fmul_rn(gA.x, frc));
            float a2 = __fadd_rn(__fmul_rn(fA.y, w0), __fmul_rn(gA.y, frc));
            a1v[j] = a1; a2v[j] = a2;
            b0v[j] = __fadd_rn(__fmul_rn(fA.z, w0), __fmul_rn(gA.z, frc));
            b1v[j] = __fadd_rn(__fmul_rn(fA.w, w0), __fmul_rn(gA.w, frc));
            b2v[j] = __fadd_rn(__fmul_rn(fB.x, w0), __fmul_rn(gB.x, frc));

            // --- fused pass1 affine recurrence (same fmaf forms as before) ---
            float yp = fmaf(-a1, yp1, fmaf(-a2, yp2, dj));
            float uu = fmaf(-a1, u1, -(a2 * u2));
            float vv = fmaf(-a1, v1, -(a2 * v2));
            yp2 = yp1; yp1 = yp;
            u2 = u1; u1 = uu;
            v2 = v1; v1 = vv;
        }

        size_t base = vbase + (size_t)g * 8;
        float4* dptr = (float4*)(out + base);
        dptr[0] = make_float4(dryv[0], dryv[1], dryv[2], dryv[3]);
        dptr[1] = make_float4(dryv[4], dryv[5], dryv[6], dryv[7]);
        float4* eptr = (float4*)(out + 2ull * BS * NS + base);
        eptr[0] = make_float4(envv[0], envv[1], envv[2], envv[3]);
        eptr[1] = make_float4(envv[4], envv[5], envv[6], envv[7]);
        float4* aptr = (float4*)(out + 4ull * BS * NS + base * 3);
        aptr[0] = make_float4(1.0f, a1v[0], a2v[0], 1.0f);
        aptr[1] = make_float4(a1v[1], a2v[1], 1.0f, a1v[2]);
        aptr[2] = make_float4(a2v[2], 1.0f, a1v[3], a2v[3]);
        aptr[3] = make_float4(1.0f, a1v[4], a2v[4], 1.0f);
        aptr[4] = make_float4(a1v[5], a2v[5], 1.0f, a1v[6]);
        aptr[5] = make_float4(a2v[6], 1.0f, a1v[7], a2v[7]);
        float4* bptr = (float4*)(out + 7ull * BS * NS + base * 3);
        bptr[0] = make_float4(b0v[0], b1v[0], b2v[0], b0v[1]);
        bptr[1] = make_float4(b1v[1], b2v[1], b0v[2], b1v[2]);
        bptr[2] = make_float4(b2v[2], b0v[3], b1v[3], b2v[3]);
        bptr[3] = make_float4(b0v[4], b1v[4], b2v[4], b0v[5]);
        bptr[4] = make_float4(b1v[5], b2v[5], b0v[6], b1v[6]);
        bptr[5] = make_float4(b2v[6], b0v[7], b1v[7], b2v[7]);
    }

    float* o = g_chunk + (size_t)tid * 6;
    o[0] = u1; o[1] = v1; o[2] = u2; o[3] = v2; o[4] = yp1; o[5] = yp2;
}

// ---------------- K2: per-voice affine scan (smem-staged, same op order) ----------------
__global__ void k_scan2() {
    __shared__ float sm[NCH * 7];      // stride-7 records: conflict-free across lanes
    int b = blockIdx.x;
    const float* raw = g_chunk + (size_t)b * NCH * 6;
    for (int idx = threadIdx.x; idx < NCH * 6; idx += blockDim.x) {
        int chunk = idx / 6;
        int f = idx - chunk * 6;
        int lane = chunk >> 5;
        int cpos = chunk & 31;
        sm[(cpos * 32 + lane) * 7 + f] = raw[idx];
    }
    __syncthreads();
    if (threadIdx.x < 32) {
        int lane = threadIdx.x;
        const int G = NCH / 32;        // 32

        float m00 = 1.f, m01 = 0.f, m10 = 0.f, m11 = 1.f, p0 = 0.f, p1 = 0.f;
#pragma unroll 1
        for (int c = 0; c < G; c++) {
            const float* rec = &sm[(c * 32 + lane) * 7];
            float c00 = rec[0], c01 = rec[1], c10 = rec[2], c11 = rec[3], r0 = rec[4], r1 = rec[5];
            float n00 = __fmaf_rn(c00, m00, __fmul_rn(c01, m10));
            float n01 = __fmaf_rn(c00, m01, __fmul_rn(c01, m11));
            float n10 = __fmaf_rn(c10, m00, __fmul_rn(c11, m10));
            float n11 = __fmaf_rn(c10, m01, __fmul_rn(c11, m11));
            float np0 = __fadd_rn(__fmaf_rn(c00, p0, __fmul_rn(c01, p1)), r0);
            float np1 = __fadd_rn(__fmaf_rn(c10, p0, __fmul_rn(c11, p1)), r1);
            m00 = n00; m01 = n01; m10 = n10; m11 = n11; p0 = np0; p1 = np1;
        }
#pragma unroll
        for (int d = 1; d < 32; d <<= 1) {
            float e00 = __shfl_up_sync(0xffffffffu, m00, d);
            float e01 = __shfl_up_sync(0xffffffffu, m01, d);
            float e10 = __shfl_up_sync(0xffffffffu, m10, d);
            float e11 = __shfl_up_sync(0xffffffffu, m11, d);
            float ep0 = __shfl_up_sync(0xffffffffu, p0, d);
            float ep1 = __shfl_up_sync(0xffffffffu, p1, d);
            if (lane >= d) {
                float n00 = __fmaf_rn(m00, e00, __fmul_rn(m01, e10));
                float n01 = __fmaf_rn(m00, e01, __fmul_rn(m01, e11));
                float n10 = __fmaf_rn(m10, e00, __fmul_rn(m11, e10));
                float n11 = __fmaf_rn(m10, e01, __fmul_rn(m11, e11));
                float np0 = __fadd_rn(__fmaf_rn(m00, ep0, __fmul_rn(m01, ep1)), p0);
                float np1 = __fadd_rn(__fmaf_rn(m10, ep0, __fmul_rn(m11, ep1)), p1);
                m00 = n00; m01 = n01; m10 = n10; m11 = n11; p0 = np0; p1 = np1;
            }
        }
        float s0 = __shfl_up_sync(0xffffffffu, p0, 1);
        float s1 = __shfl_up_sync(0xffffffffu, p1, 1);
        if (lane == 0) { s0 = 0.f; s1 = 0.f; }

#pragma unroll 1
        for (int c = 0; c < G; c++) {
            g_init[(size_t)b * NCH + lane * G + c] = make_float2(s0, s1);
            const float* rec = &sm[(c * 32 + lane) * 7];
            float c00 = rec[0], c01 = rec[1], c10 = rec[2], c11 = rec[3], r0 = rec[4], r1 = rec[5];
            float ns0 = __fadd_rn(__fmaf_rn(c00, s0, __fmul_rn(c01, s1)), r0);
            float ns1 = __fadd_rn(__fmaf_rn(c10, s0, __fmul_rn(c11, s1)), r1);
            s0 = ns0; s1 = ns1;
        }
    }
}

// ---------------- K3: pass 2 — IIR replay (exact ref rounding) + FIR + tanh ----------------
__global__ void k_pass2(float* __restrict__ out) {
    int tid = blockIdx.x * blockDim.x + threadIdx.x;
    if (tid >= BS * NCH) return;
    int b = tid >> 10;
    int c = tid & (NCH - 1);
    size_t base = (size_t)b * NS + (size_t)c * CHUNK;
    const float* dry = out + base;
    const float* a3 = out + 4ull * BS * NS + base * 3;
    const float* b3 = out + 7ull * BS * NS + base * 3;
    float* w_wet = out + 1ull * BS * NS + base;
    float* w_yab = out + 3ull * BS * NS + base;
    float* w_ya = out + 10ull * BS * NS + base;

    float2 ini = g_init[tid];
    float y1 = ini.x, y2 = ini.y;
    float dg = g_bp[b].dist;

#pragma unroll 1
    for (int g = 0; g < CHUNK; g += 8) {
        float4 x0 = *(const float4*)(dry + g);
        float4 x1 = *(const float4*)(dry + g + 4);
        float4 A[6], B[6];
#pragma unroll
        for (int q = 0; q < 6; q++) A[q] = *(const float4*)(a3 + 3 * g + 4 * q);
#pragma unroll
        for (int q = 0; q < 6; q++) B[q] = *(const float4*)(b3 + 3 * g + 4 * q);
        const float* af = (const float*)A;
        const float* bf = (const float*)B;
        float xs[8] = {x0.x, x0.y, x0.z, x0.w, x1.x, x1.y, x1.z, x1.w};
        float ya[8], yb[8], wt[8];
#pragma unroll
        for (int j = 0; j < 8; j++) {
            float a1 = af[3 * j + 1], a2 = af[3 * j + 2];
            float c0 = bf[3 * j], c1 = bf[3 * j + 1], c2 = bf[3 * j + 2];
            float y = __fsub_rn(__fsub_rn(xs[j], __fmul_rn(a1, y1)), __fmul_rn(a2, y2));
            float v = __fadd_rn(__fadd_rn(__fmul_rn(c0, y), __fmul_rn(c1, y1)),
                                __fmul_rn(c2, y2));
            ya[j] = y; yb[j] = v;
            wt[j] = xla_tanh(__fmul_rn(v, dg));
            y2 = y1; y1 = y;
        }
        ((float4*)(w_ya + g))[0] = make_float4(ya[0], ya[1], ya[2], ya[3]);
        ((float4*)(w_ya + g))[1] = make_float4(ya[4], ya[5], ya[6], ya[7]);
        ((float4*)(w_yab + g))[0] = make_float4(yb[0], yb[1], yb[2], yb[3]);
        ((float4*)(w_yab + g))[1] = make_float4(yb[4], yb[5], yb[6], yb[7]);
        ((float4*)(w_wet + g))[0] = make_float4(wt[0], wt[1], wt[2], wt[3]);
        ((float4*)(w_wet + g))[1] = make_float4(wt[4], wt[5], wt[6], wt[7]);
    }
}

extern "C" void kernel_launch(void* const* d_in, const int* in_sizes, int n_in,
                              void* d_out, int out_size) {
    const float* f0_hz = (const float*)d_in[0];
    const float* note_on = (const float*)d_in[1];
    const float* phase = (const float*)d_in[2];
    const float* logits = (const float*)d_in[3];
    const float* osc_shape = (const float*)d_in[4];
    const float* osc_gain = (const float*)d_in[5];
    const float* dist_gain = (const float*)d_in[6];
    const float* learned_alpha = (const float*)d_in[7];
    float* out = (float*)d_out;

    k_prep<<<(BS * NF + 255) / 256, 256>>>(f0_hz, note_on, phase, logits,
                                           osc_shape, osc_gain, dist_gain, learned_alpha);
    k_mainp1<<<(BS * NCH + 127) / 128, 128>>>(out);
    k_scan2<<<BS, 256>>>();
    k_pass2<<<(BS * NCH + 127) / 128, 128>>>(out);
}

// round 6
// speedup vs baseline: 1.5006x; 1.4712x over previous
#include <cuda_runtime.h>
#include <math.h>
#include <stdint.h>

#define BS 32
#define NS 65536
#define NF 128
#define CHUNK 16
#define NCH (NS / CHUNK)      // 4096
#define SRf 48000.0f
#define STAB 0.999f

// Output plane offsets (elements of BS*NS):
// dry=0, wet=1, env=2, y_ab=3, a_coeff3=4..6, b_coeff=7..9, y_a=10

struct BParam {
    float inc, phase, kk, shp;
    float sm, gain, dur, alpha;
    float dist, pad0, pad1, pad2;
};

__device__ BParam g_bp[BS];
__device__ float4 g_frame[BS * NF * 2];   // per frame: {a1,a2,b0,b1},{b2,-,-,-}
__device__ float  g_chunk[BS * NCH * 6];  // u1,v1,u2,v2,yp1,yp2
__device__ float2 g_init[BS * NCH];

// ---- XLA rational tanh (Eigen fast tanh) ----
__device__ __forceinline__ float xla_tanh(float x) {
    const float kClamp = 7.90531110763549805f;
    float xc = fminf(fmaxf(x, -kClamp), kClamp);
    float x2 = __fmul_rn(xc, xc);
    float p = __fadd_rn(2.00018790482477e-13f, __fmul_rn(x2, -2.76076847742355e-16f));
    p = __fadd_rn(-8.60467152213735e-11f, __fmul_rn(x2, p));
    p = __fadd_rn(5.12229709037114e-08f,  __fmul_rn(x2, p));
    p = __fadd_rn(1.48572235717979e-05f,  __fmul_rn(x2, p));
    p = __fadd_rn(6.37261928875436e-04f,  __fmul_rn(x2, p));
    p = __fadd_rn(4.89352455891786e-03f,  __fmul_rn(x2, p));
    float num = __fmul_rn(xc, p);
    float q = __fadd_rn(1.18534705686654e-04f, __fmul_rn(x2, 1.19825839466702e-06f));
    q = __fadd_rn(2.26843463243900e-03f, __fmul_rn(x2, q));
    q = __fadd_rn(4.89352518554385e-03f, __fmul_rn(x2, q));
    float r = __fdiv_rn(num, q);
    return (fabsf(x) < 0.0004f) ? x : r;
}

// ---- XLA-CPU-style sin/cos: range reduce with single-f32 2*pi, then accurate ----
__device__ __forceinline__ float xla_sin(float x) {
    float k = rintf(__fmul_rn(x, 0.15915494309189535f));
    float r = fmaf(-k, 6.28318548202514648f, x);
    return sinf(r);
}
__device__ __forceinline__ float xla_cos(float x) {
    float k = rintf(__fmul_rn(x, 0.15915494309189535f));
    float r = fmaf(-k, 6.28318548202514648f, x);
    return cosf(r);
}

// Chain over bits >=4 of v (v multiple of 16, v>0): MSB->LSB rounded adds.
// Prefix of the full associative-scan cumsum chain -> bit-exact base.
__device__ __forceinline__ float cum_base4(float c, unsigned v) {
    int msb = 31 - __clz(v);
    float r = c * __int_as_float((127 + msb) << 23);
#pragma unroll 1
    for (int k = msb - 1; k >= 4; k--) {
        if ((v >> k) & 1u)
            r = __fadd_rn(r, c * __int_as_float((127 + k) << 23));
    }
    return r;
}

// ---------------- K0: per-batch params + per-frame biquad coeffs ----------------
__global__ void k_prep(const float* __restrict__ f0_hz,
                       const float* __restrict__ durp,
                       const float* __restrict__ phasep,
                       const float* __restrict__ logits,
                       const float* __restrict__ shpp,
                       const float* __restrict__ gainp,
                       const float* __restrict__ distp,
                       const float* __restrict__ alphap) {
    int tid = blockIdx.x * blockDim.x + threadIdx.x;
    if (tid >= BS * NF) return;
    int b = tid / NF;
    int f = tid - b * NF;
    const float* lg = logits + (size_t)tid * 5;
    float th0 = xla_tanh(lg[0]);
    float a1 = __fmul_rn(__fmul_rn(2.0f, th0), STAB);
    float a1a = fabsf(a1);
    float th1 = xla_tanh(lg[1]);
    float a2 = __fdiv_rn(__fadd_rn(__fmul_rn(__fmul_rn(__fsub_rn(2.0f, a1a), th1), STAB), a1a), 2.0f);
    g_frame[tid * 2]     = make_float4(a1, a2, lg[2], lg[3]);
    g_frame[tid * 2 + 1] = make_float4(lg[4], 0.f, 0.f, 0.f);
    if (f == 0) {
        BParam p;
        float f0 = f0_hz[b];
        p.inc = __fdiv_rn(f0, SRf);
        p.phase = phasep[b];
        float partials = __fdiv_rn(12000.0f, __fmul_rn(f0, log10f(f0)));
        p.kk = __fmul_rn(3.14159274101257324f, partials);
        p.shp = shpp[b];
        p.sm = __fsub_rn(1.0f, __fmul_rn(shpp[b], 0.5f));
        p.gain = gainp[b];
        p.dur = durp[b];
        p.alpha = alphap[b];
        p.dist = distp[b];
        g_bp[b] = p;
    }
}

// ---------------- K1: osc + env + coeff interp + FUSED pass1 affine ----------------
// one thread = one 16-sample chunk
__global__ void k_mainp1(float* __restrict__ out) {
    int tid = blockIdx.x * blockDim.x + threadIdx.x;
    if (tid >= BS * NCH) return;
    int b = tid >> 12;                 // NCH = 4096
    int c = tid & (NCH - 1);
    int s0 = c << 4;
    BParam p = g_bp[b];

    // cumsum bases (bit-exact prefix chains over bits >= 4)
    float inc = p.inc;
    float i8 = inc * 8.0f, i4 = inc * 4.0f, i2 = inc * 2.0f;
    float baseA = (s0 == 0) ? 0.0f : cum_base4(inc, (unsigned)s0);
    float baseB = cum_base4(inc, (unsigned)(s0 + 16));

    // hoist frame loads: i0 spans at most one boundary within 16 samples
    float pos0 = __fmul_rn((float)s0, 127.0f / 65535.0f);
    int i0s = (int)floorf(pos0);
    i0s = min(i0s, 126);
    int i2x = min(i0s + 2, 127);
    float4 F0a = g_frame[(b * NF + i0s) * 2],     F0b = g_frame[(b * NF + i0s) * 2 + 1];
    float4 F1a = g_frame[(b * NF + i0s + 1) * 2], F1b = g_frame[(b * NF + i0s + 1) * 2 + 1];
    float4 F2a = g_frame[(b * NF + i2x) * 2],     F2b = g_frame[(b * NF + i2x) * 2 + 1];

    // affine recurrence state (pass1)
    float yp1 = 0.f, yp2 = 0.f, u1 = 1.f, u2 = 0.f, v1 = 0.f, v2 = 1.f;

    size_t vbase = (size_t)b * NS + s0;

#pragma unroll 1
    for (int g = 0; g < 2; g++) {
        float dryv[8], envv[8], a1v[8], a2v[8], b0v[8], b1v[8], b2v[8];
#pragma unroll
        for (int j = 0; j < 8; j++) {
            int jj = g * 8 + j;
            int i = s0 + jj;
            unsigned l = (unsigned)(jj + 1);
            // --- phase: bit-exact associative_scan cumsum (hoisted bases) ---
            float cum = (l < 16u) ? baseA : baseB;
            if (l & 8u)  cum = __fadd_rn(cum, i8);
            if (l & 4u)  cum = __fadd_rn(cum, i4);
            if (l & 2u)  cum = __fadd_rn(cum, i2);
            if (l & 1u)  cum = __fadd_rn(cum, inc);
            float arg = __fadd_rn(__fmul_rn(6.28318548202514648f, cum), p.phase);
            float s = xla_sin(arg);
            float cc = xla_cos(__fmul_rn(arg, 0.5f));
            float sq = xla_tanh(__fdiv_rn(__fmul_rn(p.kk, s), 2.0f));
            float vco = __fmul_rn(__fmul_rn(p.sm, sq),
                                  __fadd_rn(1.0f, __fmul_rn(p.shp, cc)));

            // --- envelope ---
            float tt = __fdiv_rn((float)i, SRf);
            float ramp = __fsub_rn(1.0f, __fdiv_rn(tt, p.dur));
            ramp = fminf(fmaxf(ramp, 0.001f), 1.0f);
            float env = powf(ramp, p.alpha);
            if (!(tt <= p.dur)) env = 0.0f;
            envv[j] = env;
            float dj = __fmul_rn(__fmul_rn(vco, p.gain), env);
            dryv[j] = dj;

            // --- frame interpolation (identical values via hoisted frames) ---
            float pos = __fmul_rn((float)i, 127.0f / 65535.0f);
            float i0f = floorf(pos);
            int i0 = (int)i0f;
            i0 = min(i0, 126);
            float frc = __fsub_rn(pos, (float)i0);
            float w0 = __fsub_rn(1.0f, frc);
            bool hi = (i0 != i0s);
            float4 fA = hi ? F1a : F0a;
            float4 fB = hi ? F1b : F0b;
            float4 gA = hi ? F2a : F1a;
            float4 gB = hi ? F2b : F1b;
            float a1 = __fadd_rn(__fmul_rn(fA.x, w0), __fmul_rn(gA.x, frc));
            float a2 = __fadd_rn(__fmul_rn(fA.y, w0), __fmul_rn(gA.y, frc));
            a1v[j] = a1; a2v[j] = a2;
            b0v[j] = __fadd_rn(__fmul_rn(fA.z, w0), __fmul_rn(gA.z, frc));
            b1v[j] = __fadd_rn(__fmul_rn(fA.w, w0), __fmul_rn(gA.w, frc));
            b2v[j] = __fadd_rn(__fmul_rn(fB.x, w0), __fmul_rn(gB.x, frc));

            // --- fused pass1 affine recurrence ---
            float yp = fmaf(-a1, yp1, fmaf(-a2, yp2, dj));
            float uu = fmaf(-a1, u1, -(a2 * u2));
            float vv = fmaf(-a1, v1, -(a2 * v2));
            yp2 = yp1; yp1 = yp;
            u2 = u1; u1 = uu;
            v2 = v1; v1 = vv;
        }

        size_t base = vbase + (size_t)g * 8;
        float4* dptr = (float4*)(out + base);
        dptr[0] = make_float4(dryv[0], dryv[1], dryv[2], dryv[3]);
        dptr[1] = make_float4(dryv[4], dryv[5], dryv[6], dryv[7]);
        float4* eptr = (float4*)(out + 2ull * BS * NS + base);
        eptr[0] = make_float4(envv[0], envv[1], envv[2], envv[3]);
        eptr[1] = make_float4(envv[4], envv[5], envv[6], envv[7]);
        float4* aptr = (float4*)(out + 4ull * BS * NS + base * 3);
        aptr[0] = make_float4(1.0f, a1v[0], a2v[0], 1.0f);
        aptr[1] = make_float4(a1v[1], a2v[1], 1.0f, a1v[2]);
        aptr[2] = make_float4(a2v[2], 1.0f, a1v[3], a2v[3]);
        aptr[3] = make_float4(1.0f, a1v[4], a2v[4], 1.0f);
        aptr[4] = make_float4(a1v[5], a2v[5], 1.0f, a1v[6]);
        aptr[5] = make_float4(a2v[6], 1.0f, a1v[7], a2v[7]);
        float4* bptr = (float4*)(out + 7ull * BS * NS + base * 3);
        bptr[0] = make_float4(b0v[0], b1v[0], b2v[0], b0v[1]);
        bptr[1] = make_float4(b1v[1], b2v[1], b0v[2], b1v[2]);
        bptr[2] = make_float4(b2v[2], b0v[3], b1v[3], b2v[3]);
        bptr[3] = make_float4(b0v[4], b1v[4], b2v[4], b0v[5]);
        bptr[4] = make_float4(b1v[5], b2v[5], b0v[6], b1v[6]);
        bptr[5] = make_float4(b2v[6], b0v[7], b1v[7], b2v[7]);
    }

    float* o = g_chunk + (size_t)tid * 6;
    o[0] = u1; o[1] = v1; o[2] = u2; o[3] = v2; o[4] = yp1; o[5] = yp2;
}

// ---------------- K2: per-voice affine scan (dynamic smem staged) ----------------
__global__ void k_scan2() {
    extern __shared__ float sm[];      // NCH*7 floats, stride-7 records
    int b = blockIdx.x;
    const float* raw = g_chunk + (size_t)b * NCH * 6;
    const int G = NCH / 32;            // 128 chunks per lane
    for (int idx = threadIdx.x; idx < NCH * 6; idx += blockDim.x) {
        int chunk = idx / 6;
        int f = idx - chunk * 6;
        int lane = chunk / G;          // owning lane (contiguous in time)
        int cpos = chunk - lane * G;
        sm[(cpos * 32 + lane) * 7 + f] = raw[idx];
    }
    __syncthreads();
    if (threadIdx.x < 32) {
        int lane = threadIdx.x;

        float m00 = 1.f, m01 = 0.f, m10 = 0.f, m11 = 1.f, p0 = 0.f, p1 = 0.f;
#pragma unroll 1
        for (int c = 0; c < G; c++) {
            const float* rec = &sm[(c * 32 + lane) * 7];
            float c00 = rec[0], c01 = rec[1], c10 = rec[2], c11 = rec[3], r0 = rec[4], r1 = rec[5];
            float n00 = __fmaf_rn(c00, m00, __fmul_rn(c01, m10));
            float n01 = __fmaf_rn(c00, m01, __fmul_rn(c01, m11));
            float n10 = __fmaf_rn(c10, m00, __fmul_rn(c11, m10));
            float n11 = __fmaf_rn(c10, m01, __fmul_rn(c11, m11));
            float np0 = __fadd_rn(__fmaf_rn(c00, p0, __fmul_rn(c01, p1)), r0);
            float np1 = __fadd_rn(__fmaf_rn(c10, p0, __fmul_rn(c11, p1)), r1);
            m00 = n00; m01 = n01; m10 = n10; m11 = n11; p0 = np0; p1 = np1;
        }
#pragma unroll
        for (int d = 1; d < 32; d <<= 1) {
            float e00 = __shfl_up_sync(0xffffffffu, m00, d);
            float e01 = __shfl_up_sync(0xffffffffu, m01, d);
            float e10 = __shfl_up_sync(0xffffffffu, m10, d);
            float e11 = __shfl_up_sync(0xffffffffu, m11, d);
            float ep0 = __shfl_up_sync(0xffffffffu, p0, d);
            float ep1 = __shfl_up_sync(0xffffffffu, p1, d);
            if (lane >= d) {
                float n00 = __fmaf_rn(m00, e00, __fmul_rn(m01, e10));
                float n01 = __fmaf_rn(m00, e01, __fmul_rn(m01, e11));
                float n10 = __fmaf_rn(m10, e00, __fmul_rn(m11, e10));
                float n11 = __fmaf_rn(m10, e01, __fmul_rn(m11, e11));
                float np0 = __fadd_rn(__fmaf_rn(m00, ep0, __fmul_rn(m01, ep1)), p0);
                float np1 = __fadd_rn(__fmaf_rn(m10, ep0, __fmul_rn(m11, ep1)), p1);
                m00 = n00; m01 = n01; m10 = n10; m11 = n11; p0 = np0; p1 = np1;
            }
        }
        float s0 = __shfl_up_sync(0xffffffffu, p0, 1);
        float s1 = __shfl_up_sync(0xffffffffu, p1, 1);
        if (lane == 0) { s0 = 0.f; s1 = 0.f; }

#pragma unroll 1
        for (int c = 0; c < G; c++) {
            g_init[(size_t)b * NCH + lane * G + c] = make_float2(s0, s1);
            const float* rec = &sm[(c * 32 + lane) * 7];
            float c00 = rec[0], c01 = rec[1], c10 = rec[2], c11 = rec[3], r0 = rec[4], r1 = rec[5];
            float ns0 = __fadd_rn(__fmaf_rn(c00, s0, __fmul_rn(c01, s1)), r0);
            float ns1 = __fadd_rn(__fmaf_rn(c10, s0, __fmul_rn(c11, s1)), r1);
            s0 = ns0; s1 = ns1;
        }
    }
}

// ---------------- K3: pass 2 — IIR replay (exact ref rounding) + FIR + tanh ----------------
__global__ void k_pass2(float* __restrict__ out) {
    int tid = blockIdx.x * blockDim.x + threadIdx.x;
    if (tid >= BS * NCH) return;
    int b = tid >> 12;
    int c = tid & (NCH - 1);
    size_t base = (size_t)b * NS + (size_t)c * CHUNK;
    const float* dry = out + base;
    const float* a3 = out + 4ull * BS * NS + base * 3;
    const float* b3 = out + 7ull * BS * NS + base * 3;
    float* w_wet = out + 1ull * BS * NS + base;
    float* w_yab = out + 3ull * BS * NS + base;
    float* w_ya = out + 10ull * BS * NS + base;

    float2 ini = g_init[tid];
    float y1 = ini.x, y2 = ini.y;
    float dg = g_bp[b].dist;

#pragma unroll
    for (int g = 0; g < CHUNK; g += 8) {
        float4 x0 = *(const float4*)(dry + g);
        float4 x1 = *(const float4*)(dry + g + 4);
        float4 A[6], B[6];
#pragma unroll
        for (int q = 0; q < 6; q++) A[q] = *(const float4*)(a3 + 3 * g + 4 * q);
#pragma unroll
        for (int q = 0; q < 6; q++) B[q] = *(const float4*)(b3 + 3 * g + 4 * q);
        const float* af = (const float*)A;
        const float* bf = (const float*)B;
        float xs[8] = {x0.x, x0.y, x0.z, x0.w, x1.x, x1.y, x1.z, x1.w};
        float ya[8], yb[8], wt[8];
#pragma unroll
        for (int j = 0; j < 8; j++) {
            float a1 = af[3 * j + 1], a2 = af[3 * j + 2];
            float c0 = bf[3 * j], c1 = bf[3 * j + 1], c2 = bf[3 * j + 2];
            float y = __fsub_rn(__fsub_rn(xs[j], __fmul_rn(a1, y1)), __fmul_rn(a2, y2));
            float v = __fadd_rn(__fadd_rn(__fmul_rn(c0, y), __fmul_rn(c1, y1)),
                                __fmul_rn(c2, y2));
            ya[j] = y; yb[j] = v;
            wt[j] = xla_tanh(__fmul_rn(v, dg));
            y2 = y1; y1 = y;
        }
        ((float4*)(w_ya + g))[0] = make_float4(ya[0], ya[1], ya[2], ya[3]);
        ((float4*)(w_ya + g))[1] = make_float4(ya[4], ya[5], ya[6], ya[7]);
        ((float4*)(w_yab + g))[0] = make_float4(yb[0], yb[1], yb[2], yb[3]);
        ((float4*)(w_yab + g))[1] = make_float4(yb[4], yb[5], yb[6], yb[7]);
        ((float4*)(w_wet + g))[0] = make_float4(wt[0], wt[1], wt[2], wt[3]);
        ((float4*)(w_wet + g))[1] = make_float4(wt[4], wt[5], wt[6], wt[7]);
    }
}

extern "C" void kernel_launch(void* const* d_in, const int* in_sizes, int n_in,
                              void* d_out, int out_size) {
    const float* f0_hz = (const float*)d_in[0];
    const float* note_on = (const float*)d_in[1];
    const float* phase = (const float*)d_in[2];
    const float* logits = (const float*)d_in[3];
    const float* osc_shape = (const float*)d_in[4];
    const float* osc_gain = (const float*)d_in[5];
    const float* dist_gain = (const float*)d_in[6];
    const float* learned_alpha = (const float*)d_in[7];
    float* out = (float*)d_out;

    static int smem_set = 0;
    const int scan_smem = NCH * 7 * sizeof(float);   // 114688 B
    if (!smem_set) {
        cudaFuncSetAttribute(k_scan2, cudaFuncAttributeMaxDynamicSharedMemorySize, scan_smem);
        smem_set = 1;
    }

    k_prep<<<(BS * NF + 255) / 256, 256>>>(f0_hz, note_on, phase, logits,
                                           osc_shape, osc_gain, dist_gain, learned_alpha);
    k_mainp1<<<(BS * NCH + 127) / 128, 128>>>(out);
    k_scan2<<<BS, 512, scan_smem>>>();
    k_pass2<<<(BS * NCH + 127) / 128, 128>>>(out);
}

// round 7
// speedup vs baseline: 1.6852x; 1.1230x over previous
#include <cuda_runtime.h>
#include <math.h>
#include <stdint.h>

#define BS 32
#define NS 65536
#define NF 128
#define CHUNK 8
#define NCH (NS / CHUNK)      // 8192
#define SRf 48000.0f
#define STAB 0.999f

// Output plane offsets (elements of BS*NS):
// dry=0, wet=1, env=2, y_ab=3, a_coeff3=4..6, b_coeff=7..9, y_a=10

struct BParam {
    float inc, phase, kk, shp;
    float sm, gain, dur, alpha;
    float dist, pad0, pad1, pad2;
};

__device__ BParam g_bp[BS];
__device__ float4 g_frame[BS * NF * 2];   // per frame: {a1,a2,b0,b1},{b2,-,-,-}
__device__ float  g_chunk[BS * NCH * 6];  // u1,v1,u2,v2,yp1,yp2
__device__ float2 g_init[BS * NCH];

// ---- XLA rational tanh (Eigen fast tanh) ----
__device__ __forceinline__ float xla_tanh(float x) {
    const float kClamp = 7.90531110763549805f;
    float xc = fminf(fmaxf(x, -kClamp), kClamp);
    float x2 = __fmul_rn(xc, xc);
    float p = __fadd_rn(2.00018790482477e-13f, __fmul_rn(x2, -2.76076847742355e-16f));
    p = __fadd_rn(-8.60467152213735e-11f, __fmul_rn(x2, p));
    p = __fadd_rn(5.12229709037114e-08f,  __fmul_rn(x2, p));
    p = __fadd_rn(1.48572235717979e-05f,  __fmul_rn(x2, p));
    p = __fadd_rn(6.37261928875436e-04f,  __fmul_rn(x2, p));
    p = __fadd_rn(4.89352455891786e-03f,  __fmul_rn(x2, p));
    float num = __fmul_rn(xc, p);
    float q = __fadd_rn(1.18534705686654e-04f, __fmul_rn(x2, 1.19825839466702e-06f));
    q = __fadd_rn(2.26843463243900e-03f, __fmul_rn(x2, q));
    q = __fadd_rn(4.89352518554385e-03f, __fmul_rn(x2, q));
    float r = __fdiv_rn(num, q);
    return (fabsf(x) < 0.0004f) ? x : r;
}

// ---- XLA-CPU-style sin/cos: range reduce with single-f32 2*pi, then accurate ----
__device__ __forceinline__ float xla_sin(float x) {
    float k = rintf(__fmul_rn(x, 0.15915494309189535f));
    float r = fmaf(-k, 6.28318548202514648f, x);
    return sinf(r);
}
__device__ __forceinline__ float xla_cos(float x) {
    float k = rintf(__fmul_rn(x, 0.15915494309189535f));
    float r = fmaf(-k, 6.28318548202514648f, x);
    return cosf(r);
}

// Chain over bits >=3 of v (v multiple of 8, v>0): MSB->LSB rounded adds.
// Prefix of the full associative-scan cumsum chain -> bit-exact base.
__device__ __forceinline__ float cum_base3(float c, unsigned v) {
    int msb = 31 - __clz(v);
    float r = c * __int_as_float((127 + msb) << 23);
#pragma unroll 1
    for (int k = msb - 1; k >= 3; k--) {
        if ((v >> k) & 1u)
            r = __fadd_rn(r, c * __int_as_float((127 + k) << 23));
    }
    return r;
}

// ---------------- K0: per-batch params + per-frame biquad coeffs ----------------
__global__ void k_prep(const float* __restrict__ f0_hz,
                       const float* __restrict__ durp,
                       const float* __restrict__ phasep,
                       const float* __restrict__ logits,
                       const float* __restrict__ shpp,
                       const float* __restrict__ gainp,
                       const float* __restrict__ distp,
                       const float* __restrict__ alphap) {
    int tid = blockIdx.x * blockDim.x + threadIdx.x;
    if (tid >= BS * NF) return;
    int b = tid / NF;
    int f = tid - b * NF;
    const float* lg = logits + (size_t)tid * 5;
    float th0 = xla_tanh(lg[0]);
    float a1 = __fmul_rn(__fmul_rn(2.0f, th0), STAB);
    float a1a = fabsf(a1);
    float th1 = xla_tanh(lg[1]);
    float a2 = __fdiv_rn(__fadd_rn(__fmul_rn(__fmul_rn(__fsub_rn(2.0f, a1a), th1), STAB), a1a), 2.0f);
    g_frame[tid * 2]     = make_float4(a1, a2, lg[2], lg[3]);
    g_frame[tid * 2 + 1] = make_float4(lg[4], 0.f, 0.f, 0.f);
    if (f == 0) {
        BParam p;
        float f0 = f0_hz[b];
        p.inc = __fdiv_rn(f0, SRf);
        p.phase = phasep[b];
        float partials = __fdiv_rn(12000.0f, __fmul_rn(f0, log10f(f0)));
        p.kk = __fmul_rn(3.14159274101257324f, partials);
        p.shp = shpp[b];
        p.sm = __fsub_rn(1.0f, __fmul_rn(shpp[b], 0.5f));
        p.gain = gainp[b];
        p.dur = durp[b];
        p.alpha = alphap[b];
        p.dist = distp[b];
        g_bp[b] = p;
    }
}

// ---------------- K1: osc + env + coeff interp + FUSED pass1 affine ----------------
// one thread = one 8-sample chunk
__global__ void k_mainp1(float* __restrict__ out) {
    int tid = blockIdx.x * blockDim.x + threadIdx.x;
    if (tid >= BS * NCH) return;
    int b = tid >> 13;                 // NCH = 8192
    int c = tid & (NCH - 1);
    int s0 = c << 3;
    BParam p = g_bp[b];

    // hoist frame loads: i0 spans at most one boundary within 8 samples
    float pos0 = __fmul_rn((float)s0, 127.0f / 65535.0f);
    int i0s = (int)floorf(pos0);
    i0s = min(i0s, 126);
    int i2x = min(i0s + 2, 127);
    float4 F0a = g_frame[(b * NF + i0s) * 2],     F0b = g_frame[(b * NF + i0s) * 2 + 1];
    float4 F1a = g_frame[(b * NF + i0s + 1) * 2], F1b = g_frame[(b * NF + i0s + 1) * 2 + 1];
    float4 F2a = g_frame[(b * NF + i2x) * 2],     F2b = g_frame[(b * NF + i2x) * 2 + 1];

    // affine recurrence state (pass1)
    float yp1 = 0.f, yp2 = 0.f, u1 = 1.f, u2 = 0.f, v1 = 0.f, v2 = 1.f;

    float dryv[8], envv[8], a1v[8], a2v[8], b0v[8], b1v[8], b2v[8];

    // dead-chunk test: tt monotone; if first sample past note-off, whole chunk is
    float tt0 = __fdiv_rn((float)s0, SRf);
    bool alive = (tt0 <= p.dur);

    if (alive) {
        // cumsum bases (bit-exact prefix chains over bits >= 3)
        float inc = p.inc;
        float i4 = inc * 4.0f, i2 = inc * 2.0f;
        float baseA = (s0 == 0) ? 0.0f : cum_base3(inc, (unsigned)s0);
        float baseB = cum_base3(inc, (unsigned)(s0 + 8));
#pragma unroll
        for (int j = 0; j < 8; j++) {
            int i = s0 + j;
            unsigned l = (unsigned)(j + 1);
            float cum = (l < 8u) ? baseA : baseB;
            if (l & 4u)  cum = __fadd_rn(cum, i4);
            if (l & 2u)  cum = __fadd_rn(cum, i2);
            if (l & 1u)  cum = __fadd_rn(cum, inc);
            float arg = __fadd_rn(__fmul_rn(6.28318548202514648f, cum), p.phase);
            float s = xla_sin(arg);
            float cc = xla_cos(__fmul_rn(arg, 0.5f));
            float sq = xla_tanh(__fdiv_rn(__fmul_rn(p.kk, s), 2.0f));
            float vco = __fmul_rn(__fmul_rn(p.sm, sq),
                                  __fadd_rn(1.0f, __fmul_rn(p.shp, cc)));

            float tt = __fdiv_rn((float)i, SRf);
            float ramp = __fsub_rn(1.0f, __fdiv_rn(tt, p.dur));
            ramp = fminf(fmaxf(ramp, 0.001f), 1.0f);
            float env = powf(ramp, p.alpha);
            if (!(tt <= p.dur)) env = 0.0f;
            envv[j] = env;
            dryv[j] = __fmul_rn(__fmul_rn(vco, p.gain), env);

            float pos = __fmul_rn((float)i, 127.0f / 65535.0f);
            int i0 = (int)floorf(pos);
            i0 = min(i0, 126);
            float frc = __fsub_rn(pos, (float)i0);
            float w0 = __fsub_rn(1.0f, frc);
            bool hi = (i0 != i0s);
            float4 fA = hi ? F1a : F0a;
            float4 fB = hi ? F1b : F0b;
            float4 gA = hi ? F2a : F1a;
            float4 gB = hi ? F2b : F1b;
            float a1 = __fadd_rn(__fmul_rn(fA.x, w0), __fmul_rn(gA.x, frc));
            float a2 = __fadd_rn(__fmul_rn(fA.y, w0), __fmul_rn(gA.y, frc));
            a1v[j] = a1; a2v[j] = a2;
            b0v[j] = __fadd_rn(__fmul_rn(fA.z, w0), __fmul_rn(gA.z, frc));
            b1v[j] = __fadd_rn(__fmul_rn(fA.w, w0), __fmul_rn(gA.w, frc));
            b2v[j] = __fadd_rn(__fmul_rn(fB.x, w0), __fmul_rn(gB.x, frc));

            float dj = dryv[j];
            float yp = fmaf(-a1, yp1, fmaf(-a2, yp2, dj));
            float uu = fmaf(-a1, u1, -(a2 * u2));
            float vv = fmaf(-a1, v1, -(a2 * v2));
            yp2 = yp1; yp1 = yp;
            u2 = u1; u1 = uu;
            v2 = v1; v1 = vv;
        }
    } else {
        // dead chunk: env=0, dry=0 exactly; coeffs + recurrence (x=0) only
#pragma unroll
        for (int j = 0; j < 8; j++) {
            int i = s0 + j;
            envv[j] = 0.0f;
            dryv[j] = 0.0f;
            float pos = __fmul_rn((float)i, 127.0f / 65535.0f);
            int i0 = (int)floorf(pos);
            i0 = min(i0, 126);
            float frc = __fsub_rn(pos, (float)i0);
            float w0 = __fsub_rn(1.0f, frc);
            bool hi = (i0 != i0s);
            float4 fA = hi ? F1a : F0a;
            float4 fB = hi ? F1b : F0b;
            float4 gA = hi ? F2a : F1a;
            float4 gB = hi ? F2b : F1b;
            float a1 = __fadd_rn(__fmul_rn(fA.x, w0), __fmul_rn(gA.x, frc));
            float a2 = __fadd_rn(__fmul_rn(fA.y, w0), __fmul_rn(gA.y, frc));
            a1v[j] = a1; a2v[j] = a2;
            b0v[j] = __fadd_rn(__fmul_rn(fA.z, w0), __fmul_rn(gA.z, frc));
            b1v[j] = __fadd_rn(__fmul_rn(fA.w, w0), __fmul_rn(gA.w, frc));
            b2v[j] = __fadd_rn(__fmul_rn(fB.x, w0), __fmul_rn(gB.x, frc));

            float yp = fmaf(-a1, yp1, fmaf(-a2, yp2, 0.0f));
            float uu = fmaf(-a1, u1, -(a2 * u2));
            float vv = fmaf(-a1, v1, -(a2 * v2));
            yp2 = yp1; yp1 = yp;
            u2 = u1; u1 = uu;
            v2 = v1; v1 = vv;
        }
    }

    size_t base = (size_t)b * NS + s0;
    float4* dptr = (float4*)(out + base);
    dptr[0] = make_float4(dryv[0], dryv[1], dryv[2], dryv[3]);
    dptr[1] = make_float4(dryv[4], dryv[5], dryv[6], dryv[7]);
    float4* eptr = (float4*)(out + 2ull * BS * NS + base);
    eptr[0] = make_float4(envv[0], envv[1], envv[2], envv[3]);
    eptr[1] = make_float4(envv[4], envv[5], envv[6], envv[7]);
    float4* aptr = (float4*)(out + 4ull * BS * NS + base * 3);
    aptr[0] = make_float4(1.0f, a1v[0], a2v[0], 1.0f);
    aptr[1] = make_float4(a1v[1], a2v[1], 1.0f, a1v[2]);
    aptr[2] = make_float4(a2v[2], 1.0f, a1v[3], a2v[3]);
    aptr[3] = make_float4(1.0f, a1v[4], a2v[4], 1.0f);
    aptr[4] = make_float4(a1v[5], a2v[5], 1.0f, a1v[6]);
    aptr[5] = make_float4(a2v[6], 1.0f, a1v[7], a2v[7]);
    float4* bptr = (float4*)(out + 7ull * BS * NS + base * 3);
    bptr[0] = make_float4(b0v[0], b1v[0], b2v[0], b0v[1]);
    bptr[1] = make_float4(b1v[1], b2v[1], b0v[2], b1v[2]);
    bptr[2] = make_float4(b2v[2], b0v[3], b1v[3], b2v[3]);
    bptr[3] = make_float4(b0v[4], b1v[4], b2v[4], b0v[5]);
    bptr[4] = make_float4(b1v[5], b2v[5], b0v[6], b1v[6]);
    bptr[5] = make_float4(b2v[6], b0v[7], b1v[7], b2v[7]);

    float* o = g_chunk + (size_t)tid * 6;
    o[0] = u1; o[1] = v1; o[2] = u2; o[3] = v2; o[4] = yp1; o[5] = yp2;
}

// ---------------- K2: per-voice affine scan (dynamic smem staged) ----------------
__global__ void k_scan2() {
    extern __shared__ float sm[];      // NCH*7 floats, stride-7 records
    int b = blockIdx.x;
    const float* raw = g_chunk + (size_t)b * NCH * 6;
    const int G = NCH / 32;            // 256 chunks per lane
    for (int idx = threadIdx.x; idx < NCH * 6; idx += blockDim.x) {
        int chunk = idx / 6;
        int f = idx - chunk * 6;
        int lane = chunk / G;          // owning lane (contiguous in time)
        int cpos = chunk - lane * G;
        sm[(cpos * 32 + lane) * 7 + f] = raw[idx];
    }
    __syncthreads();
    if (threadIdx.x < 32) {
        int lane = threadIdx.x;

        float m00 = 1.f, m01 = 0.f, m10 = 0.f, m11 = 1.f, p0 = 0.f, p1 = 0.f;
#pragma unroll 1
        for (int c = 0; c < G; c++) {
            const float* rec = &sm[(c * 32 + lane) * 7];
            float c00 = rec[0], c01 = rec[1], c10 = rec[2], c11 = rec[3], r0 = rec[4], r1 = rec[5];
            float n00 = __fmaf_rn(c00, m00, __fmul_rn(c01, m10));
            float n01 = __fmaf_rn(c00, m01, __fmul_rn(c01, m11));
            float n10 = __fmaf_rn(c10, m00, __fmul_rn(c11, m10));
            float n11 = __fmaf_rn(c10, m01, __fmul_rn(c11, m11));
            float np0 = __fadd_rn(__fmaf_rn(c00, p0, __fmul_rn(c01, p1)), r0);
            float np1 = __fadd_rn(__fmaf_rn(c10, p0, __fmul_rn(c11, p1)), r1);
            m00 = n00; m01 = n01; m10 = n10; m11 = n11; p0 = np0; p1 = np1;
        }
#pragma unroll
        for (int d = 1; d < 32; d <<= 1) {
            float e00 = __shfl_up_sync(0xffffffffu, m00, d);
            float e01 = __shfl_up_sync(0xffffffffu, m01, d);
            float e10 = __shfl_up_sync(0xffffffffu, m10, d);
            float e11 = __shfl_up_sync(0xffffffffu, m11, d);
            float ep0 = __shfl_up_sync(0xffffffffu, p0, d);
            float ep1 = __shfl_up_sync(0xffffffffu, p1, d);
            if (lane >= d) {
                float n00 = __fmaf_rn(m00, e00, __fmul_rn(m01, e10));
                float n01 = __fmaf_rn(m00, e01, __fmul_rn(m01, e11));
                float n10 = __fmaf_rn(m10, e00, __fmul_rn(m11, e10));
                float n11 = __fmaf_rn(m10, e01, __fmul_rn(m11, e11));
                float np0 = __fadd_rn(__fmaf_rn(m00, ep0, __fmul_rn(m01, ep1)), p0);
                float np1 = __fadd_rn(__fmaf_rn(m10, ep0, __fmul_rn(m11, ep1)), p1);
                m00 = n00; m01 = n01; m10 = n10; m11 = n11; p0 = np0; p1 = np1;
            }
        }
        float s0 = __shfl_up_sync(0xffffffffu, p0, 1);
        float s1 = __shfl_up_sync(0xffffffffu, p1, 1);
        if (lane == 0) { s0 = 0.f; s1 = 0.f; }

#pragma unroll 1
        for (int c = 0; c < G; c++) {
            g_init[(size_t)b * NCH + lane * G + c] = make_float2(s0, s1);
            const float* rec = &sm[(c * 32 + lane) * 7];
            float c00 = rec[0], c01 = rec[1], c10 = rec[2], c11 = rec[3], r0 = rec[4], r1 = rec[5];
            float ns0 = __fadd_rn(__fmaf_rn(c00, s0, __fmul_rn(c01, s1)), r0);
            float ns1 = __fadd_rn(__fmaf_rn(c10, s0, __fmul_rn(c11, s1)), r1);
            s0 = ns0; s1 = ns1;
        }
    }
}

// ---------------- K3: pass 2 — IIR replay (exact ref rounding) + FIR + tanh ----------------
__global__ void k_pass2(float* __restrict__ out) {
    int tid = blockIdx.x * blockDim.x + threadIdx.x;
    if (tid >= BS * NCH) return;
    int b = tid >> 13;
    int c = tid & (NCH - 1);
    size_t base = (size_t)b * NS + (size_t)c * CHUNK;
    const float* dry = out + base;
    const float* a3 = out + 4ull * BS * NS + base * 3;
    const float* b3 = out + 7ull * BS * NS + base * 3;
    float* w_wet = out + 1ull * BS * NS + base;
    float* w_yab = out + 3ull * BS * NS + base;
    float* w_ya = out + 10ull * BS * NS + base;

    float2 ini = g_init[tid];
    float y1 = ini.x, y2 = ini.y;
    float dg = g_bp[b].dist;

    float4 x0 = *(const float4*)(dry);
    float4 x1 = *(const float4*)(dry + 4);
    float4 A[6], B[6];
#pragma unroll
    for (int q = 0; q < 6; q++) A[q] = *(const float4*)(a3 + 4 * q);
#pragma unroll
    for (int q = 0; q < 6; q++) B[q] = *(const float4*)(b3 + 4 * q);
    const float* af = (const float*)A;
    const float* bf = (const float*)B;
    float xs[8] = {x0.x, x0.y, x0.z, x0.w, x1.x, x1.y, x1.z, x1.w};
    float ya[8], yb[8], wt[8];
#pragma unroll
    for (int j = 0; j < 8; j++) {
        float a1 = af[3 * j + 1], a2 = af[3 * j + 2];
        float c0 = bf[3 * j], c1 = bf[3 * j + 1], c2 = bf[3 * j + 2];
        float y = __fsub_rn(__fsub_rn(xs[j], __fmul_rn(a1, y1)), __fmul_rn(a2, y2));
        float v = __fadd_rn(__fadd_rn(__fmul_rn(c0, y), __fmul_rn(c1, y1)),
                            __fmul_rn(c2, y2));
        ya[j] = y; yb[j] = v;
        wt[j] = xla_tanh(__fmul_rn(v, dg));
        y2 = y1; y1 = y;
    }
    ((float4*)w_ya)[0] = make_float4(ya[0], ya[1], ya[2], ya[3]);
    ((float4*)w_ya)[1] = make_float4(ya[4], ya[5], ya[6], ya[7]);
    ((float4*)w_yab)[0] = make_float4(yb[0], yb[1], yb[2], yb[3]);
    ((float4*)w_yab)[1] = make_float4(yb[4], yb[5], yb[6], yb[7]);
    ((float4*)w_wet)[0] = make_float4(wt[0], wt[1], wt[2], wt[3]);
    ((float4*)w_wet)[1] = make_float4(wt[4], wt[5], wt[6], wt[7]);
}

extern "C" void kernel_launch(void* const* d_in, const int* in_sizes, int n_in,
                              void* d_out, int out_size) {
    const float* f0_hz = (const float*)d_in[0];
    const float* note_on = (const float*)d_in[1];
    const float* phase = (const float*)d_in[2];
    const float* logits = (const float*)d_in[3];
    const float* osc_shape = (const float*)d_in[4];
    const float* osc_gain = (const float*)d_in[5];
    const float* dist_gain = (const float*)d_in[6];
    const float* learned_alpha = (const float*)d_in[7];
    float* out = (float*)d_out;

    static int smem_set = 0;
    const int scan_smem = NCH * 7 * sizeof(float);   // 229376 B
    if (!smem_set) {
        cudaFuncSetAttribute(k_scan2, cudaFuncAttributeMaxDynamicSharedMemorySize, scan_smem);
        smem_set = 1;
    }

    k_prep<<<(BS * NF + 255) / 256, 256>>>(f0_hz, note_on, phase, logits,
                                           osc_shape, osc_gain, dist_gain, learned_alpha);
    k_mainp1<<<(BS * NCH + 127) / 128, 128>>>(out);
    k_scan2<<<BS, 1024, scan_smem>>>();
    k_pass2<<<(BS * NCH + 127) / 128, 128>>>(out);
}

// round 8
// speedup vs baseline: 1.8369x; 1.0900x over previous
#include <cuda_runtime.h>
#include <math.h>
#include <stdint.h>

#define BS 32
#define NS 65536
#define NF 128
#define CHUNK 8
#define NCH (NS / CHUNK)      // 8192
#define SRf 48000.0f
#define STAB 0.999f

// Output plane offsets (elements of BS*NS):
// dry=0, wet=1, env=2, y_ab=3, a_coeff3=4..6, b_coeff=7..9, y_a=10

struct BParam {
    float inc, phase, kk, shp;
    float sm, gain, dur, alpha;
    float dist, pad0, pad1, pad2;
};

__device__ BParam g_bp[BS];
__device__ float4 g_frame[BS * NF * 2];   // per frame: {a1,a2,b0,b1},{b2,-,-,-}
__device__ float  g_chunk[BS * NCH * 6];  // u1,v1,u2,v2,yp1,yp2
__device__ float2 g_init[BS * NCH];

// ---- XLA rational tanh (Eigen fast tanh) ----
__device__ __forceinline__ float xla_tanh(float x) {
    const float kClamp = 7.90531110763549805f;
    float xc = fminf(fmaxf(x, -kClamp), kClamp);
    float x2 = __fmul_rn(xc, xc);
    float p = __fadd_rn(2.00018790482477e-13f, __fmul_rn(x2, -2.76076847742355e-16f));
    p = __fadd_rn(-8.60467152213735e-11f, __fmul_rn(x2, p));
    p = __fadd_rn(5.12229709037114e-08f,  __fmul_rn(x2, p));
    p = __fadd_rn(1.48572235717979e-05f,  __fmul_rn(x2, p));
    p = __fadd_rn(6.37261928875436e-04f,  __fmul_rn(x2, p));
    p = __fadd_rn(4.89352455891786e-03f,  __fmul_rn(x2, p));
    float num = __fmul_rn(xc, p);
    float q = __fadd_rn(1.18534705686654e-04f, __fmul_rn(x2, 1.19825839466702e-06f));
    q = __fadd_rn(2.26843463243900e-03f, __fmul_rn(x2, q));
    q = __fadd_rn(4.89352518554385e-03f, __fmul_rn(x2, q));
    float r = __fdiv_rn(num, q);
    return (fabsf(x) < 0.0004f) ? x : r;
}

// ---- XLA-CPU-style sin/cos: range reduce with single-f32 2*pi, then accurate ----
__device__ __forceinline__ float xla_sin(float x) {
    float k = rintf(__fmul_rn(x, 0.15915494309189535f));
    float r = fmaf(-k, 6.28318548202514648f, x);
    return sinf(r);
}
__device__ __forceinline__ float xla_cos(float x) {
    float k = rintf(__fmul_rn(x, 0.15915494309189535f));
    float r = fmaf(-k, 6.28318548202514648f, x);
    return cosf(r);
}

// Chain over bits >=3 of v (v multiple of 8, v>0): MSB->LSB rounded adds.
// Prefix of the full associative-scan cumsum chain -> bit-exact base.
__device__ __forceinline__ float cum_base3(float c, unsigned v) {
    int msb = 31 - __clz(v);
    float r = c * __int_as_float((127 + msb) << 23);
#pragma unroll 1
    for (int k = msb - 1; k >= 3; k--) {
        if ((v >> k) & 1u)
            r = __fadd_rn(r, c * __int_as_float((127 + k) << 23));
    }
    return r;
}

// ---------------- K0: per-batch params + per-frame biquad coeffs ----------------
__global__ void k_prep(const float* __restrict__ f0_hz,
                       const float* __restrict__ durp,
                       const float* __restrict__ phasep,
                       const float* __restrict__ logits,
                       const float* __restrict__ shpp,
                       const float* __restrict__ gainp,
                       const float* __restrict__ distp,
                       const float* __restrict__ alphap) {
    int tid = blockIdx.x * blockDim.x + threadIdx.x;
    if (tid >= BS * NF) return;
    int b = tid / NF;
    int f = tid - b * NF;
    const float* lg = logits + (size_t)tid * 5;
    float th0 = xla_tanh(lg[0]);
    float a1 = __fmul_rn(__fmul_rn(2.0f, th0), STAB);
    float a1a = fabsf(a1);
    float th1 = xla_tanh(lg[1]);
    float a2 = __fdiv_rn(__fadd_rn(__fmul_rn(__fmul_rn(__fsub_rn(2.0f, a1a), th1), STAB), a1a), 2.0f);
    g_frame[tid * 2]     = make_float4(a1, a2, lg[2], lg[3]);
    g_frame[tid * 2 + 1] = make_float4(lg[4], 0.f, 0.f, 0.f);
    if (f == 0) {
        BParam p;
        float f0 = f0_hz[b];
        p.inc = __fdiv_rn(f0, SRf);
        p.phase = phasep[b];
        float partials = __fdiv_rn(12000.0f, __fmul_rn(f0, log10f(f0)));
        p.kk = __fmul_rn(3.14159274101257324f, partials);
        p.shp = shpp[b];
        p.sm = __fsub_rn(1.0f, __fmul_rn(shpp[b], 0.5f));
        p.gain = gainp[b];
        p.dur = durp[b];
        p.alpha = alphap[b];
        p.dist = distp[b];
        g_bp[b] = p;
    }
}

// ---------------- K1: osc + env + coeff interp + FUSED pass1 affine ----------------
// one thread = one 8-sample chunk
__global__ void k_mainp1(float* __restrict__ out) {
    int tid = blockIdx.x * blockDim.x + threadIdx.x;
    if (tid >= BS * NCH) return;
    int b = tid >> 13;                 // NCH = 8192
    int c = tid & (NCH - 1);
    int s0 = c << 3;
    BParam p = g_bp[b];

    // hoist frame loads: i0 spans at most one boundary within 8 samples
    float pos0 = __fmul_rn((float)s0, 127.0f / 65535.0f);
    int i0s = (int)floorf(pos0);
    i0s = min(i0s, 126);
    int i2x = min(i0s + 2, 127);
    float4 F0a = g_frame[(b * NF + i0s) * 2],     F0b = g_frame[(b * NF + i0s) * 2 + 1];
    float4 F1a = g_frame[(b * NF + i0s + 1) * 2], F1b = g_frame[(b * NF + i0s + 1) * 2 + 1];
    float4 F2a = g_frame[(b * NF + i2x) * 2],     F2b = g_frame[(b * NF + i2x) * 2 + 1];

    // affine recurrence state (pass1)
    float yp1 = 0.f, yp2 = 0.f, u1 = 1.f, u2 = 0.f, v1 = 0.f, v2 = 1.f;

    float dryv[8], envv[8], a1v[8], a2v[8], b0v[8], b1v[8], b2v[8];

    // dead-chunk test: tt monotone; if first sample past note-off, whole chunk is
    float tt0 = __fdiv_rn((float)s0, SRf);
    bool alive = (tt0 <= p.dur);

    if (alive) {
        // cumsum bases (bit-exact prefix chains over bits >= 3)
        float inc = p.inc;
        float i4 = inc * 4.0f, i2 = inc * 2.0f;
        float baseA = (s0 == 0) ? 0.0f : cum_base3(inc, (unsigned)s0);
        float baseB = cum_base3(inc, (unsigned)(s0 + 8));
#pragma unroll
        for (int j = 0; j < 8; j++) {
            int i = s0 + j;
            unsigned l = (unsigned)(j + 1);
            float cum = (l < 8u) ? baseA : baseB;
            if (l & 4u)  cum = __fadd_rn(cum, i4);
            if (l & 2u)  cum = __fadd_rn(cum, i2);
            if (l & 1u)  cum = __fadd_rn(cum, inc);
            float arg = __fadd_rn(__fmul_rn(6.28318548202514648f, cum), p.phase);
            float s = xla_sin(arg);
            float cc = xla_cos(__fmul_rn(arg, 0.5f));
            float sq = xla_tanh(__fdiv_rn(__fmul_rn(p.kk, s), 2.0f));
            float vco = __fmul_rn(__fmul_rn(p.sm, sq),
                                  __fadd_rn(1.0f, __fmul_rn(p.shp, cc)));

            float tt = __fdiv_rn((float)i, SRf);
            float ramp = __fsub_rn(1.0f, __fdiv_rn(tt, p.dur));
            ramp = fminf(fmaxf(ramp, 0.001f), 1.0f);
            float env = __powf(ramp, p.alpha);
            if (!(tt <= p.dur)) env = 0.0f;
            envv[j] = env;
            dryv[j] = __fmul_rn(__fmul_rn(vco, p.gain), env);

            float pos = __fmul_rn((float)i, 127.0f / 65535.0f);
            int i0 = (int)floorf(pos);
            i0 = min(i0, 126);
            float frc = __fsub_rn(pos, (float)i0);
            float w0 = __fsub_rn(1.0f, frc);
            bool hi = (i0 != i0s);
            float4 fA = hi ? F1a : F0a;
            float4 fB = hi ? F1b : F0b;
            float4 gA = hi ? F2a : F1a;
            float4 gB = hi ? F2b : F1b;
            float a1 = __fadd_rn(__fmul_rn(fA.x, w0), __fmul_rn(gA.x, frc));
            float a2 = __fadd_rn(__fmul_rn(fA.y, w0), __fmul_rn(gA.y, frc));
            a1v[j] = a1; a2v[j] = a2;
            b0v[j] = __fadd_rn(__fmul_rn(fA.z, w0), __fmul_rn(gA.z, frc));
            b1v[j] = __fadd_rn(__fmul_rn(fA.w, w0), __fmul_rn(gA.w, frc));
            b2v[j] = __fadd_rn(__fmul_rn(fB.x, w0), __fmul_rn(gB.x, frc));

            float dj = dryv[j];
            float yp = fmaf(-a1, yp1, fmaf(-a2, yp2, dj));
            float uu = fmaf(-a1, u1, -(a2 * u2));
            float vv = fmaf(-a1, v1, -(a2 * v2));
            yp2 = yp1; yp1 = yp;
            u2 = u1; u1 = uu;
            v2 = v1; v1 = vv;
        }
    } else {
        // dead chunk: env=0, dry=0 exactly; coeffs + recurrence (x=0) only
#pragma unroll
        for (int j = 0; j < 8; j++) {
            int i = s0 + j;
            envv[j] = 0.0f;
            dryv[j] = 0.0f;
            float pos = __fmul_rn((float)i, 127.0f / 65535.0f);
            int i0 = (int)floorf(pos);
            i0 = min(i0, 126);
            float frc = __fsub_rn(pos, (float)i0);
            float w0 = __fsub_rn(1.0f, frc);
            bool hi = (i0 != i0s);
            float4 fA = hi ? F1a : F0a;
            float4 fB = hi ? F1b : F0b;
            float4 gA = hi ? F2a : F1a;
            float4 gB = hi ? F2b : F1b;
            float a1 = __fadd_rn(__fmul_rn(fA.x, w0), __fmul_rn(gA.x, frc));
            float a2 = __fadd_rn(__fmul_rn(fA.y, w0), __fmul_rn(gA.y, frc));
            a1v[j] = a1; a2v[j] = a2;
            b0v[j] = __fadd_rn(__fmul_rn(fA.z, w0), __fmul_rn(gA.z, frc));
            b1v[j] = __fadd_rn(__fmul_rn(fA.w, w0), __fmul_rn(gA.w, frc));
            b2v[j] = __fadd_rn(__fmul_rn(fB.x, w0), __fmul_rn(gB.x, frc));

            float yp = fmaf(-a1, yp1, fmaf(-a2, yp2, 0.0f));
            float uu = fmaf(-a1, u1, -(a2 * u2));
            float vv = fmaf(-a1, v1, -(a2 * v2));
            yp2 = yp1; yp1 = yp;
            u2 = u1; u1 = uu;
            v2 = v1; v1 = vv;
        }
    }

    size_t base = (size_t)b * NS + s0;
    float4* dptr = (float4*)(out + base);
    dptr[0] = make_float4(dryv[0], dryv[1], dryv[2], dryv[3]);
    dptr[1] = make_float4(dryv[4], dryv[5], dryv[6], dryv[7]);
    float4* eptr = (float4*)(out + 2ull * BS * NS + base);
    eptr[0] = make_float4(envv[0], envv[1], envv[2], envv[3]);
    eptr[1] = make_float4(envv[4], envv[5], envv[6], envv[7]);
    float4* aptr = (float4*)(out + 4ull * BS * NS + base * 3);
    aptr[0] = make_float4(1.0f, a1v[0], a2v[0], 1.0f);
    aptr[1] = make_float4(a1v[1], a2v[1], 1.0f, a1v[2]);
    aptr[2] = make_float4(a2v[2], 1.0f, a1v[3], a2v[3]);
    aptr[3] = make_float4(1.0f, a1v[4], a2v[4], 1.0f);
    aptr[4] = make_float4(a1v[5], a2v[5], 1.0f, a1v[6]);
    aptr[5] = make_float4(a2v[6], 1.0f, a1v[7], a2v[7]);
    float4* bptr = (float4*)(out + 7ull * BS * NS + base * 3);
    bptr[0] = make_float4(b0v[0], b1v[0], b2v[0], b0v[1]);
    bptr[1] = make_float4(b1v[1], b2v[1], b0v[2], b1v[2]);
    bptr[2] = make_float4(b2v[2], b0v[3], b1v[3], b2v[3]);
    bptr[3] = make_float4(b0v[4], b1v[4], b2v[4], b0v[5]);
    bptr[4] = make_float4(b1v[5], b2v[5], b0v[6], b1v[6]);
    bptr[5] = make_float4(b2v[6], b0v[7], b1v[7], b2v[7]);

    float* o = g_chunk + (size_t)tid * 6;
    o[0] = u1; o[1] = v1; o[2] = u2; o[3] = v2; o[4] = yp1; o[5] = yp2;
}

// ---------------- K2: per-voice affine scan (dynamic smem staged) ----------------
__global__ void k_scan2() {
    extern __shared__ float sm[];      // NCH*7 floats, stride-7 records
    int b = blockIdx.x;
    const float* raw = g_chunk + (size_t)b * NCH * 6;
    const int G = NCH / 32;            // 256 chunks per lane
    for (int idx = threadIdx.x; idx < NCH * 6; idx += blockDim.x) {
        int chunk = idx / 6;
        int f = idx - chunk * 6;
        int lane = chunk / G;          // owning lane (contiguous in time)
        int cpos = chunk - lane * G;
        sm[(cpos * 32 + lane) * 7 + f] = raw[idx];
    }
    __syncthreads();
    if (threadIdx.x < 32) {
        int lane = threadIdx.x;

        float m00 = 1.f, m01 = 0.f, m10 = 0.f, m11 = 1.f, p0 = 0.f, p1 = 0.f;
#pragma unroll 1
        for (int c = 0; c < G; c++) {
            const float* rec = &sm[(c * 32 + lane) * 7];
            float c00 = rec[0], c01 = rec[1], c10 = rec[2], c11 = rec[3], r0 = rec[4], r1 = rec[5];
            float n00 = __fmaf_rn(c00, m00, __fmul_rn(c01, m10));
            float n01 = __fmaf_rn(c00, m01, __fmul_rn(c01, m11));
            float n10 = __fmaf_rn(c10, m00, __fmul_rn(c11, m10));
            float n11 = __fmaf_rn(c10, m01, __fmul_rn(c11, m11));
            float np0 = __fadd_rn(__fmaf_rn(c00, p0, __fmul_rn(c01, p1)), r0);
            float np1 = __fadd_rn(__fmaf_rn(c10, p0, __fmul_rn(c11, p1)), r1);
            m00 = n00; m01 = n01; m10 = n10; m11 = n11; p0 = np0; p1 = np1;
        }
#pragma unroll
        for (int d = 1; d < 32; d <<= 1) {
            float e00 = __shfl_up_sync(0xffffffffu, m00, d);
            float e01 = __shfl_up_sync(0xffffffffu, m01, d);
            float e10 = __shfl_up_sync(0xffffffffu, m10, d);
            float e11 = __shfl_up_sync(0xffffffffu, m11, d);
            float ep0 = __shfl_up_sync(0xffffffffu, p0, d);
            float ep1 = __shfl_up_sync(0xffffffffu, p1, d);
            if (lane >= d) {
                float n00 = __fmaf_rn(m00, e00, __fmul_rn(m01, e10));
                float n01 = __fmaf_rn(m00, e01, __fmul_rn(m01, e11));
                float n10 = __fmaf_rn(m10, e00, __fmul_rn(m11, e10));
                float n11 = __fmaf_rn(m10, e01, __fmul_rn(m11, e11));
                float np0 = __fadd_rn(__fmaf_rn(m00, ep0, __fmul_rn(m01, ep1)), p0);
                float np1 = __fadd_rn(__fmaf_rn(m10, ep0, __fmul_rn(m11, ep1)), p1);
                m00 = n00; m01 = n01; m10 = n10; m11 = n11; p0 = np0; p1 = np1;
            }
        }
        float s0 = __shfl_up_sync(0xffffffffu, p0, 1);
        float s1 = __shfl_up_sync(0xffffffffu, p1, 1);
        if (lane == 0) { s0 = 0.f; s1 = 0.f; }

#pragma unroll 1
        for (int c = 0; c < G; c++) {
            g_init[(size_t)b * NCH + lane * G + c] = make_float2(s0, s1);
            const float* rec = &sm[(c * 32 + lane) * 7];
            float c00 = rec[0], c01 = rec[1], c10 = rec[2], c11 = rec[3], r0 = rec[4], r1 = rec[5];
            float ns0 = __fadd_rn(__fmaf_rn(c00, s0, __fmul_rn(c01, s1)), r0);
            float ns1 = __fadd_rn(__fmaf_rn(c10, s0, __fmul_rn(c11, s1)), r1);
            s0 = ns0; s1 = ns1;
        }
    }
}

// ---------------- K3: pass 2 — coeff recompute + IIR replay + FIR + tanh ----------------
__global__ void k_pass2(float* __restrict__ out) {
    int tid = blockIdx.x * blockDim.x + threadIdx.x;
    if (tid >= BS * NCH) return;
    int b = tid >> 13;
    int c = tid & (NCH - 1);
    int s0 = c << 3;
    size_t base = (size_t)b * NS + s0;
    const float* dry = out + base;
    float* w_wet = out + 1ull * BS * NS + base;
    float* w_yab = out + 3ull * BS * NS + base;
    float* w_ya = out + 10ull * BS * NS + base;

    // recompute interpolated coeffs from g_frame (bit-identical to mainp1)
    float pos0 = __fmul_rn((float)s0, 127.0f / 65535.0f);
    int i0s = (int)floorf(pos0);
    i0s = min(i0s, 126);
    int i2x = min(i0s + 2, 127);
    float4 F0a = g_frame[(b * NF + i0s) * 2],     F0b = g_frame[(b * NF + i0s) * 2 + 1];
    float4 F1a = g_frame[(b * NF + i0s + 1) * 2], F1b = g_frame[(b * NF + i0s + 1) * 2 + 1];
    float4 F2a = g_frame[(b * NF + i2x) * 2],     F2b = g_frame[(b * NF + i2x) * 2 + 1];

    float2 ini = g_init[tid];
    float y1 = ini.x, y2 = ini.y;
    float dg = g_bp[b].dist;

    float4 x0 = *(const float4*)(dry);
    float4 x1 = *(const float4*)(dry + 4);
    float xs[8] = {x0.x, x0.y, x0.z, x0.w, x1.x, x1.y, x1.z, x1.w};
    float ya[8], yb[8], wt[8];
#pragma unroll
    for (int j = 0; j < 8; j++) {
        int i = s0 + j;
        float pos = __fmul_rn((float)i, 127.0f / 65535.0f);
        int i0 = (int)floorf(pos);
        i0 = min(i0, 126);
        float frc = __fsub_rn(pos, (float)i0);
        float w0 = __fsub_rn(1.0f, frc);
        bool hi = (i0 != i0s);
        float4 fA = hi ? F1a : F0a;
        float4 fB = hi ? F1b : F0b;
        float4 gA = hi ? F2a : F1a;
        float4 gB = hi ? F2b : F1b;
        float a1 = __fadd_rn(__fmul_rn(fA.x, w0), __fmul_rn(gA.x, frc));
        float a2 = __fadd_rn(__fmul_rn(fA.y, w0), __fmul_rn(gA.y, frc));
        float c0 = __fadd_rn(__fmul_rn(fA.z, w0), __fmul_rn(gA.z, frc));
        float c1 = __fadd_rn(__fmul_rn(fA.w, w0), __fmul_rn(gA.w, frc));
        float c2 = __fadd_rn(__fmul_rn(fB.x, w0), __fmul_rn(gB.x, frc));

        float y = __fsub_rn(__fsub_rn(xs[j], __fmul_rn(a1, y1)), __fmul_rn(a2, y2));
        float v = __fadd_rn(__fadd_rn(__fmul_rn(c0, y), __fmul_rn(c1, y1)),
                            __fmul_rn(c2, y2));
        ya[j] = y; yb[j] = v;
        wt[j] = xla_tanh(__fmul_rn(v, dg));
        y2 = y1; y1 = y;
    }
    ((float4*)w_ya)[0] = make_float4(ya[0], ya[1], ya[2], ya[3]);
    ((float4*)w_ya)[1] = make_float4(ya[4], ya[5], ya[6], ya[7]);
    ((float4*)w_yab)[0] = make_float4(yb[0], yb[1], yb[2], yb[3]);
    ((float4*)w_yab)[1] = make_float4(yb[4], yb[5], yb[6], yb[7]);
    ((float4*)w_wet)[0] = make_float4(wt[0], wt[1], wt[2], wt[3]);
    ((float4*)w_wet)[1] = make_float4(wt[4], wt[5], wt[6], wt[7]);
}

extern "C" void kernel_launch(void* const* d_in, const int* in_sizes, int n_in,
                              void* d_out, int out_size) {
    const float* f0_hz = (const float*)d_in[0];
    const float* note_on = (const float*)d_in[1];
    const float* phase = (const float*)d_in[2];
    const float* logits = (const float*)d_in[3];
    const float* osc_shape = (const float*)d_in[4];
    const float* osc_gain = (const float*)d_in[5];
    const float* dist_gain = (const float*)d_in[6];
    const float* learned_alpha = (const float*)d_in[7];
    float* out = (float*)d_out;

    static int smem_set = 0;
    const int scan_smem = NCH * 7 * sizeof(float);   // 229376 B
    if (!smem_set) {
        cudaFuncSetAttribute(k_scan2, cudaFuncAttributeMaxDynamicSharedMemorySize, scan_smem);
        smem_set = 1;
    }

    k_prep<<<(BS * NF + 255) / 256, 256>>>(f0_hz, note_on, phase, logits,
                                           osc_shape, osc_gain, dist_gain, learned_alpha);
    k_mainp1<<<(BS * NCH + 127) / 128, 128>>>(out);
    k_scan2<<<BS, 1024, scan_smem>>>();
    k_pass2<<<(BS * NCH + 127) / 128, 128>>>(out);
}